// round 6
// baseline (speedup 1.0000x reference)
#include <cuda_runtime.h>
#include <cuda_fp16.h>
#include <cstdint>

// Problem constants
#define GB 64
#define GN 196
#define GD 768
#define GH 12
#define GHD 64
#define GSIDE 14
#define GM (GB*GN)   // 12544

typedef unsigned long long ull;

// Scratch (device globals: allocation-free rule)
__device__ __align__(16) float  g_q[GB*GH*GN*GHD];
__device__ __align__(16) float  g_k[GB*GH*GN*GHD];
__device__ __align__(16) float  g_v[GB*GH*GN*GHD];
__device__ __align__(16) __half g_hs_h[(size_t)GM*GD];   // fp16 hidden states
__device__ __align__(16) __half g_wt_h[4*GD*GD];         // fp16 transposed weights [N][K]
__device__ __align__(16) __half g_ctx_h[(size_t)GM*GD];  // fp16 ctx

// ============================ helpers =======================================
__device__ __forceinline__ uint32_t smem_u32(const void* p) {
    uint32_t a;
    asm("{ .reg .u64 t; cvta.to.shared.u64 t, %1; cvt.u32.u64 %0, t; }" : "=r"(a) : "l"(p));
    return a;
}
__device__ __forceinline__ void cp16(uint32_t s, const void* g) {
    asm volatile("cp.async.cg.shared.global [%0], [%1], 16;" :: "r"(s), "l"(g));
}
__device__ __forceinline__ void cp_commit() { asm volatile("cp.async.commit_group;" ::: "memory"); }
__device__ __forceinline__ void cp_wait1()  { asm volatile("cp.async.wait_group 1;"  ::: "memory"); }

__device__ __forceinline__ void mma_f16(float* c, const uint32_t* a, uint32_t b0, uint32_t b1) {
    asm volatile(
        "mma.sync.aligned.m16n8k16.row.col.f32.f16.f16.f32 "
        "{%0,%1,%2,%3}, {%4,%5,%6,%7}, {%8,%9}, {%0,%1,%2,%3};"
        : "+f"(c[0]), "+f"(c[1]), "+f"(c[2]), "+f"(c[3])
        : "r"(a[0]), "r"(a[1]), "r"(a[2]), "r"(a[3]), "r"(b0), "r"(b1));
}

// packed f32x2
__device__ __forceinline__ void fma2(ull& d, ull a, ull b) {
    asm("fma.rn.f32x2 %0, %1, %2, %0;" : "+l"(d) : "l"(a), "l"(b));
}
__device__ __forceinline__ float2 unpack2(ull v) {
    float2 f;
    asm("mov.b64 {%0, %1}, %2;" : "=f"(f.x), "=f"(f.y) : "l"(v));
    return f;
}

// ===================== conversion pre-passes ================================
__global__ void conv_f2h(const float* __restrict__ s, __half* __restrict__ d, int n4) {
    int i = blockIdx.x * blockDim.x + threadIdx.x;
    if (i < n4) {
        float4 v = ((const float4*)s)[i];
        __half2 lo = __floats2half2_rn(v.x, v.y);
        __half2 hi = __floats2half2_rn(v.z, v.w);
        uint2 o;
        o.x = *(uint32_t*)&lo;
        o.y = *(uint32_t*)&hi;
        ((uint2*)d)[i] = o;
    }
}

__global__ void transpose_f2h(const float* __restrict__ S, __half* __restrict__ T) {
    __shared__ float tile[32][33];
    int tx = threadIdx.x, ty = threadIdx.y;
    int x = blockIdx.x * 32 + tx;
    int y = blockIdx.y * 32 + ty;
    #pragma unroll
    for (int j = 0; j < 32; j += 8)
        tile[ty + j][tx] = S[(size_t)(y + j) * GD + x];
    __syncthreads();
    int x2 = blockIdx.y * 32 + tx;
    int y2 = blockIdx.x * 32 + ty;
    #pragma unroll
    for (int j = 0; j < 32; j += 8)
        T[(size_t)(y2 + j) * GD + x2] = __float2half(tile[tx][ty + j]);
}

// ===================== fp16 mma.sync GEMM (round-5, unchanged) ==============
#define BM 128
#define BN 128
#define HBK 64
#define HST 72
#define HASZ (BM*HST)
#define HBSZ (BN*HST)
#define GEMM_SMEM ((2*HASZ + 2*HBSZ)*2)   // 73728 B
#define NCH (GD/HBK)                      // 12

__global__ void __launch_bounds__(256, 2)
mma_gemm_f16(const __half* __restrict__ A, const __half* __restrict__ BT,
             const float* __restrict__ bias, float* __restrict__ C, int headmode)
{
    extern __shared__ __half smh[];
    __half* As = smh;
    __half* Bs = smh + 2*HASZ;
    const uint32_t abase = smem_u32(As);
    const uint32_t bbase = smem_u32(Bs);

    const int tid = threadIdx.x;
    const int bx = blockIdx.x, by = blockIdx.y;
    const __half* Ag = A  + (size_t)(by*BM)*GD;
    const __half* Bg = BT + (size_t)(bx*BN)*GD;

    auto loadA = [&](int c, int buf) {
        const __half* ag = Ag + c*HBK;
        const uint32_t dst = abase + buf*HASZ*2;
        #pragma unroll
        for (int it = 0; it < 4; it++) {
            int idx = tid + 256*it;
            int m = idx >> 3, k8 = idx & 7;
            cp16(dst + (m*HST + k8*8)*2, ag + (size_t)m*GD + k8*8);
        }
    };
    auto loadB = [&](int c, int buf) {
        const __half* bg = Bg + c*HBK;
        const uint32_t dst = bbase + buf*HBSZ*2;
        #pragma unroll
        for (int it = 0; it < 4; it++) {
            int idx = tid + 256*it;
            int n = idx >> 3, k8 = idx & 7;
            cp16(dst + (n*HST + k8*8)*2, bg + (size_t)n*GD + k8*8);
        }
    };

    loadA(0, 0); loadB(0, 0); cp_commit();
    loadA(1, 1); loadB(1, 1); cp_commit();

    const int wid = tid >> 5, lane = tid & 31;
    const int wm = wid & 3, wn = wid >> 2;
    const int lr = lane >> 2, lq = lane & 3;

    float acc[2][8][4];
    #pragma unroll
    for (int i = 0; i < 2; i++)
        #pragma unroll
        for (int j = 0; j < 8; j++)
            #pragma unroll
            for (int k = 0; k < 4; k++) acc[i][j][k] = 0.f;

    for (int c = 0; c < NCH; c++) {
        cp_wait1();
        __syncthreads();
        const int buf = c & 1;
        const __half* as = As + buf*HASZ;
        const __half* bs = Bs + buf*HBSZ;

        #pragma unroll
        for (int s = 0; s < 4; s++) {
            const int k0 = s*16 + 2*lq;
            uint32_t a[2][4], b[8][2];
            #pragma unroll
            for (int mt = 0; mt < 2; mt++) {
                const int r = wm*32 + mt*16 + lr;
                a[mt][0] = *(const uint32_t*)&as[r*HST + k0];
                a[mt][1] = *(const uint32_t*)&as[(r+8)*HST + k0];
                a[mt][2] = *(const uint32_t*)&as[r*HST + k0 + 8];
                a[mt][3] = *(const uint32_t*)&as[(r+8)*HST + k0 + 8];
            }
            #pragma unroll
            for (int nt = 0; nt < 8; nt++) {
                const int n = wn*64 + nt*8 + lr;
                b[nt][0] = *(const uint32_t*)&bs[n*HST + k0];
                b[nt][1] = *(const uint32_t*)&bs[n*HST + k0 + 8];
            }
            #pragma unroll
            for (int mt = 0; mt < 2; mt++)
                #pragma unroll
                for (int nt = 0; nt < 8; nt++)
                    mma_f16(acc[mt][nt], a[mt], b[nt][0], b[nt][1]);
        }
        __syncthreads();
        if (c + 2 < NCH) { loadA(c+2, buf); loadB(c+2, buf); }
        cp_commit();
    }

    #pragma unroll
    for (int mt = 0; mt < 2; mt++) {
        #pragma unroll
        for (int h8 = 0; h8 < 2; h8++) {
            const int row = by*BM + wm*32 + mt*16 + h8*8 + lr;
            const int bb = row / GN, nn = row % GN;
            #pragma unroll
            for (int nt = 0; nt < 8; nt++) {
                const int col = bx*BN + wn*64 + nt*8 + 2*lq;
                float2 v;
                v.x = acc[mt][nt][h8*2+0] + bias[col];
                v.y = acc[mt][nt][h8*2+1] + bias[col+1];
                if (headmode) {
                    const int h = col >> 6, hd = col & 63;
                    *(float2*)(C + (((size_t)bb*GH + h)*GN + nn)*GHD + hd) = v;
                } else {
                    *(float2*)(C + (size_t)row*GD + col) = v;
                }
            }
        }
    }
}

// ---------------- Attention core: f32x2-packed scalar -----------------------
// One CTA per (b,h), 512 thr / 16 warps, warp handles 4 query rows per group.
// smem:
//   K2  [32][200]  float2  — K2[dp][j] = (K[j][2dp], K[j][2dp+1])
//   Vt2 [64][99]   float2  — Vt2[d][jp] = (V[2jp][d], V[2jp+1][d])
//   Qs  [196][64]  float
//   Ps  [16][4][196] float
#define KJS 200
#define VJP 99
#define K2_F   (32*KJS*2)        // floats
#define VT2_F  (64*VJP*2)
#define QS_F   (GN*GHD)
#define PS_F   (16*4*GN)
#define ATT_SMEM_BYTES ((K2_F + VT2_F + QS_F + PS_F)*4)   // 202,496 B

__global__ void __launch_bounds__(512, 1)
attn_kernel(const float* __restrict__ Q, const float* __restrict__ K,
            const float* __restrict__ V, const float* __restrict__ Wsig,
            const float* __restrict__ bsigp, const float* __restrict__ tempp,
            __half* __restrict__ CTX)
{
    extern __shared__ float smf[];
    float2* K2  = (float2*)smf;                 // 32*200 float2
    float2* Vt2 = (float2*)(smf + K2_F);        // 64*99 float2
    float*  Qs  = smf + K2_F + VT2_F;           // [196][64]
    float*  Ps  = Qs + QS_F;                    // [16][4][196]

    const int bh = blockIdx.x;
    const int b = bh / GH, h = bh % GH;
    const float* Qg = Q + (size_t)bh * GN * GHD;
    const float* Kg = K + (size_t)bh * GN * GHD;
    const float* Vg = V + (size_t)bh * GN * GHD;

    const int tid = threadIdx.x;

    // K2: idx -> (j = idx>>5, dp = idx&31); coalesced float2 global reads
    for (int idx = tid; idx < GN*32; idx += 512) {
        int j = idx >> 5, dp = idx & 31;
        K2[dp*KJS + j] = *(const float2*)&Kg[j*GHD + 2*dp];
    }
    // Vt2: idx -> (jp = idx>>6, d = idx&63)
    for (int idx = tid; idx < 98*GHD; idx += 512) {
        int jp = idx >> 6, d = idx & 63;
        float v0 = Vg[(2*jp)*GHD + d];
        float v1 = Vg[(2*jp+1)*GHD + d];
        Vt2[d*VJP + jp] = make_float2(v0, v1);
    }
    // Qs linear copy
    for (int idx = tid; idx < GN*GHD; idx += 512)
        Qs[idx] = Qg[idx];
    __syncthreads();

    const int wid = tid >> 5, lane = tid & 31;
    const float temperature = tempp[0];
    const float bs = bsigp[0];
    const float ws_lo = Wsig[lane];
    const float ws_hi = Wsig[32 + lane];

    const ull* K64 = (const ull*)K2;
    const ull* V64 = (const ull*)Vt2;

    for (int p = wid; p < GN/4; p += 16) {
        const int i0 = p * 4;

        // ---- per-row sigma -> denom ----
        float denom[4];
        #pragma unroll
        for (int r = 0; r < 4; r++) {
            int i = i0 + r;
            float part = Qs[i*64 + lane] * ws_lo + Qs[i*64 + 32 + lane] * ws_hi;
            #pragma unroll
            for (int o = 16; o > 0; o >>= 1)
                part += __shfl_xor_sync(0xffffffffu, part, o);
            float x = part + bs;
            float sp = (x > 20.f) ? x : log1pf(expf(x));
            float sig = sp + 1e-3f;
            float st = sig * temperature;
            denom[r] = 2.f * st * st;
        }

        // ---- raw scores: packed over dims; 4 rows x 7 keys per lane ----
        ull acc2[4][7];
        #pragma unroll
        for (int r = 0; r < 4; r++)
            #pragma unroll
            for (int t = 0; t < 7; t++) acc2[r][t] = 0ull;

        const ull* q0p = (const ull*)(Qs + (i0+0)*64);
        const ull* q1p = (const ull*)(Qs + (i0+1)*64);
        const ull* q2p = (const ull*)(Qs + (i0+2)*64);
        const ull* q3p = (const ull*)(Qs + (i0+3)*64);

        #pragma unroll 8
        for (int dp = 0; dp < 32; dp++) {
            const ull a0 = q0p[dp];
            const ull a1 = q1p[dp];
            const ull a2 = q2p[dp];
            const ull a3 = q3p[dp];
            const ull* kr = K64 + dp*KJS + lane;
            #pragma unroll
            for (int t = 0; t < 7; t++) {
                // j up to 223 reads past row end into written smem: finite
                // garbage, masked below before use.
                const ull kv = kr[32*t];
                fma2(acc2[0][t], a0, kv);
                fma2(acc2[1][t], a1, kv);
                fma2(acc2[2][t], a2, kv);
                fma2(acc2[3][t], a3, kv);
            }
        }

        // reduce pairs -> scalar scores
        float acc[4][7];
        #pragma unroll
        for (int r = 0; r < 4; r++)
            #pragma unroll
            for (int t = 0; t < 7; t++) {
                float2 f = unpack2(acc2[r][t]);
                acc[r][t] = f.x + f.y;
            }

        // ---- gaussian mask * score, softmax, write probs ----
        #pragma unroll
        for (int r = 0; r < 4; r++) {
            const int i = i0 + r;
            const int iy = i / GSIDE, ix = i % GSIDE;
            const float inv_denom = -1.f / denom[r];
            float mx = -1e30f;
            #pragma unroll
            for (int t = 0; t < 7; t++) {
                int j = lane + 32*t;
                if (j < GN) {
                    int jy = j / GSIDE, jx = j % GSIDE;
                    float dy = (float)(iy - jy), dx = (float)(ix - jx);
                    float d2 = dy*dy + dx*dx;
                    float val = __expf(d2 * inv_denom) * (acc[r][t] * 0.125f);
                    acc[r][t] = val;
                    mx = fmaxf(mx, val);
                } else {
                    acc[r][t] = -1e30f;
                }
            }
            #pragma unroll
            for (int o = 16; o > 0; o >>= 1)
                mx = fmaxf(mx, __shfl_xor_sync(0xffffffffu, mx, o));
            float sum = 0.f;
            #pragma unroll
            for (int t = 0; t < 7; t++) {
                int j = lane + 32*t;
                if (j < GN) {
                    float e = __expf(acc[r][t] - mx);
                    acc[r][t] = e;
                    sum += e;
                }
            }
            #pragma unroll
            for (int o = 16; o > 0; o >>= 1)
                sum += __shfl_xor_sync(0xffffffffu, sum, o);
            float inv = 1.f / sum;
            float* prow = Ps + (size_t)(wid*4 + r)*GN;
            #pragma unroll
            for (int t = 0; t < 7; t++) {
                int j = lane + 32*t;
                if (j < GN) prow[j] = acc[r][t] * inv;
            }
        }
        __syncwarp();

        // ---- ctx = P @ V : packed over key pairs; lane owns dims lane, lane+32
        ull ctx2[4][2];
        #pragma unroll
        for (int r = 0; r < 4; r++) { ctx2[r][0] = 0ull; ctx2[r][1] = 0ull; }

        const ull* p064 = (const ull*)(Ps + (size_t)(wid*4 + 0)*GN);
        const ull* p164 = (const ull*)(Ps + (size_t)(wid*4 + 1)*GN);
        const ull* p264 = (const ull*)(Ps + (size_t)(wid*4 + 2)*GN);
        const ull* p364 = (const ull*)(Ps + (size_t)(wid*4 + 3)*GN);
        const ull* vlo = V64 + (size_t)lane*VJP;
        const ull* vhi = V64 + (size_t)(lane+32)*VJP;

        #pragma unroll 7
        for (int jp = 0; jp < 98; jp++) {
            const ull va = vlo[jp];
            const ull vb = vhi[jp];
            const ull w0 = p064[jp];
            const ull w1 = p164[jp];
            const ull w2 = p264[jp];
            const ull w3 = p364[jp];
            fma2(ctx2[0][0], w0, va); fma2(ctx2[0][1], w0, vb);
            fma2(ctx2[1][0], w1, va); fma2(ctx2[1][1], w1, vb);
            fma2(ctx2[2][0], w2, va); fma2(ctx2[2][1], w2, vb);
            fma2(ctx2[3][0], w3, va); fma2(ctx2[3][1], w3, vb);
        }

        // ---- store ctx fp16 in [B,N,D] merged-head layout ----
        {
            size_t base = ((size_t)(b*GN + i0))*GD + h*GHD;
            #pragma unroll
            for (int r = 0; r < 4; r++) {
                float2 flo = unpack2(ctx2[r][0]);
                float2 fhi = unpack2(ctx2[r][1]);
                CTX[base + (size_t)r*GD + lane]      = __float2half(flo.x + flo.y);
                CTX[base + (size_t)r*GD + lane + 32] = __float2half(fhi.x + fhi.y);
            }
        }
        __syncwarp();   // Ps rows reused next group
    }
}

// ---------------- launch ----------------------------------------------------
extern "C" void kernel_launch(void* const* d_in, const int* in_sizes, int n_in,
                              void* d_out, int out_size)
{
    const float* hs   = (const float*)d_in[0];
    const float* temp = (const float*)d_in[1];
    const float* Wq   = (const float*)d_in[2];
    const float* bq   = (const float*)d_in[3];
    const float* Wk   = (const float*)d_in[4];
    const float* bk   = (const float*)d_in[5];
    const float* Wv   = (const float*)d_in[6];
    const float* bv   = (const float*)d_in[7];
    const float* Wo   = (const float*)d_in[8];
    const float* bo   = (const float*)d_in[9];
    const float* Wsig = (const float*)d_in[10];
    const float* bsig = (const float*)d_in[11];
    float* out = (float*)d_out;

    float *gq, *gk, *gv;
    __half *ghs, *gwt, *gctx;
    cudaGetSymbolAddress((void**)&gq,   g_q);
    cudaGetSymbolAddress((void**)&gk,   g_k);
    cudaGetSymbolAddress((void**)&gv,   g_v);
    cudaGetSymbolAddress((void**)&ghs,  g_hs_h);
    cudaGetSymbolAddress((void**)&gwt,  g_wt_h);
    cudaGetSymbolAddress((void**)&gctx, g_ctx_h);

    cudaFuncSetAttribute(attn_kernel,
                         cudaFuncAttributeMaxDynamicSharedMemorySize,
                         ATT_SMEM_BYTES);
    cudaFuncSetAttribute(mma_gemm_f16,
                         cudaFuncAttributeMaxDynamicSharedMemorySize,
                         GEMM_SMEM);

    __half* wtq = gwt + 0ull*GD*GD;
    __half* wtk = gwt + 1ull*GD*GD;
    __half* wtv = gwt + 2ull*GD*GD;
    __half* wto = gwt + 3ull*GD*GD;

    const int nhs4 = GM*GD/4;
    conv_f2h<<<(nhs4 + 255)/256, 256>>>(hs, ghs, nhs4);
    dim3 tb(32, 8), tg(GD/32, GD/32);
    transpose_f2h<<<tg, tb>>>(Wq, wtq);
    transpose_f2h<<<tg, tb>>>(Wk, wtk);
    transpose_f2h<<<tg, tb>>>(Wv, wtv);
    transpose_f2h<<<tg, tb>>>(Wo, wto);

    dim3 gg(GD/BN, GM/BM);   // (6, 98)
    mma_gemm_f16<<<gg, 256, GEMM_SMEM>>>(ghs,  wtq, bq, gq, 1);
    mma_gemm_f16<<<gg, 256, GEMM_SMEM>>>(ghs,  wtk, bk, gk, 1);
    mma_gemm_f16<<<gg, 256, GEMM_SMEM>>>(ghs,  wtv, bv, gv, 1);
    attn_kernel<<<GB*GH, 512, ATT_SMEM_BYTES>>>(gq, gk, gv, Wsig, bsig, temp, gctx);
    mma_gemm_f16<<<gg, 256, GEMM_SMEM>>>(gctx, wto, bo, out, 0);
}

// round 7
// speedup vs baseline: 1.0876x; 1.0876x over previous
#include <cuda_runtime.h>
#include <cuda_fp16.h>
#include <cstdint>

// Problem constants
#define GB 64
#define GN 196
#define GD 768
#define GH 12
#define GHD 64
#define GSIDE 14
#define GM (GB*GN)   // 12544

// Scratch (device globals: allocation-free rule)
__device__ __align__(16) float  g_q[GB*GH*GN*GHD];
__device__ __align__(16) float  g_k[GB*GH*GN*GHD];
__device__ __align__(16) float  g_v[GB*GH*GN*GHD];
__device__ __align__(16) __half g_hs_h[(size_t)GM*GD];   // fp16 hidden states
__device__ __align__(16) __half g_wt_h[4*GD*GD];         // fp16 transposed weights [N][K]
__device__ __align__(16) __half g_ctx_h[(size_t)GM*GD];  // fp16 ctx

// ============================ helpers =======================================
__device__ __forceinline__ uint32_t smem_u32(const void* p) {
    uint32_t a;
    asm("{ .reg .u64 t; cvta.to.shared.u64 t, %1; cvt.u32.u64 %0, t; }" : "=r"(a) : "l"(p));
    return a;
}
__device__ __forceinline__ void cp16(uint32_t s, const void* g) {
    asm volatile("cp.async.cg.shared.global [%0], [%1], 16;" :: "r"(s), "l"(g));
}
__device__ __forceinline__ void cp_commit() { asm volatile("cp.async.commit_group;" ::: "memory"); }
__device__ __forceinline__ void cp_wait1()  { asm volatile("cp.async.wait_group 1;"  ::: "memory"); }

__device__ __forceinline__ void mma_f16(float* c, const uint32_t* a, uint32_t b0, uint32_t b1) {
    asm volatile(
        "mma.sync.aligned.m16n8k16.row.col.f32.f16.f16.f32 "
        "{%0,%1,%2,%3}, {%4,%5,%6,%7}, {%8,%9}, {%0,%1,%2,%3};"
        : "+f"(c[0]), "+f"(c[1]), "+f"(c[2]), "+f"(c[3])
        : "r"(a[0]), "r"(a[1]), "r"(a[2]), "r"(a[3]), "r"(b0), "r"(b1));
}

// ===================== conversion pre-passes ================================
__global__ void conv_f2h(const float* __restrict__ s, __half* __restrict__ d, int n4) {
    int i = blockIdx.x * blockDim.x + threadIdx.x;
    if (i < n4) {
        float4 v = ((const float4*)s)[i];
        __half2 lo = __floats2half2_rn(v.x, v.y);
        __half2 hi = __floats2half2_rn(v.z, v.w);
        uint2 o;
        o.x = *(uint32_t*)&lo;
        o.y = *(uint32_t*)&hi;
        ((uint2*)d)[i] = o;
    }
}

// 4 transposes in one launch: z selects the matrix
__global__ void transpose_f2h4(const float* __restrict__ W0, const float* __restrict__ W1,
                               const float* __restrict__ W2, const float* __restrict__ W3,
                               __half* __restrict__ T)
{
    __shared__ float tile[32][33];
    const float* S = (blockIdx.z == 0) ? W0 : (blockIdx.z == 1) ? W1 :
                     (blockIdx.z == 2) ? W2 : W3;
    __half* D = T + (size_t)blockIdx.z * GD * GD;
    int tx = threadIdx.x, ty = threadIdx.y;
    int x = blockIdx.x * 32 + tx;
    int y = blockIdx.y * 32 + ty;
    #pragma unroll
    for (int j = 0; j < 32; j += 8)
        tile[ty + j][tx] = S[(size_t)(y + j) * GD + x];
    __syncthreads();
    int x2 = blockIdx.y * 32 + tx;
    int y2 = blockIdx.x * 32 + ty;
    #pragma unroll
    for (int j = 0; j < 32; j += 8)
        D[(size_t)(y2 + j) * GD + x2] = __float2half(tile[tx][ty + j]);
}

// ===================== fp16 mma.sync GEMM core ==============================
#define BM 128
#define BN 128
#define HBK 64
#define HST 72
#define HASZ (BM*HST)
#define HBSZ (BN*HST)
#define GEMM_SMEM ((2*HASZ + 2*HBSZ)*2)   // 73728 B
#define NCH (GD/HBK)                      // 12

// Shared mainloop body; epilogue differs per caller via acc handoff.
struct GemmAcc { float a[2][8][4]; };

__device__ __forceinline__ void gemm_mainloop(
    const __half* __restrict__ Ag, const __half* __restrict__ Bg,
    __half* As, __half* Bs, GemmAcc& G)
{
    const uint32_t abase = smem_u32(As);
    const uint32_t bbase = smem_u32(Bs);
    const int tid = threadIdx.x;

    auto loadA = [&](int c, int buf) {
        const __half* ag = Ag + c*HBK;
        const uint32_t dst = abase + buf*HASZ*2;
        #pragma unroll
        for (int it = 0; it < 4; it++) {
            int idx = tid + 256*it;
            int m = idx >> 3, k8 = idx & 7;
            cp16(dst + (m*HST + k8*8)*2, ag + (size_t)m*GD + k8*8);
        }
    };
    auto loadB = [&](int c, int buf) {
        const __half* bg = Bg + c*HBK;
        const uint32_t dst = bbase + buf*HBSZ*2;
        #pragma unroll
        for (int it = 0; it < 4; it++) {
            int idx = tid + 256*it;
            int n = idx >> 3, k8 = idx & 7;
            cp16(dst + (n*HST + k8*8)*2, bg + (size_t)n*GD + k8*8);
        }
    };

    loadA(0, 0); loadB(0, 0); cp_commit();
    loadA(1, 1); loadB(1, 1); cp_commit();

    const int wid = tid >> 5, lane = tid & 31;
    const int wm = wid & 3, wn = wid >> 2;
    const int lr = lane >> 2, lq = lane & 3;

    #pragma unroll
    for (int i = 0; i < 2; i++)
        #pragma unroll
        for (int j = 0; j < 8; j++)
            #pragma unroll
            for (int k = 0; k < 4; k++) G.a[i][j][k] = 0.f;

    for (int c = 0; c < NCH; c++) {
        cp_wait1();
        __syncthreads();
        const int buf = c & 1;
        const __half* as = As + buf*HASZ;
        const __half* bs = Bs + buf*HBSZ;

        #pragma unroll
        for (int s = 0; s < 4; s++) {
            const int k0 = s*16 + 2*lq;
            uint32_t a[2][4], b[8][2];
            #pragma unroll
            for (int mt = 0; mt < 2; mt++) {
                const int r = wm*32 + mt*16 + lr;
                a[mt][0] = *(const uint32_t*)&as[r*HST + k0];
                a[mt][1] = *(const uint32_t*)&as[(r+8)*HST + k0];
                a[mt][2] = *(const uint32_t*)&as[r*HST + k0 + 8];
                a[mt][3] = *(const uint32_t*)&as[(r+8)*HST + k0 + 8];
            }
            #pragma unroll
            for (int nt = 0; nt < 8; nt++) {
                const int n = wn*64 + nt*8 + lr;
                b[nt][0] = *(const uint32_t*)&bs[n*HST + k0];
                b[nt][1] = *(const uint32_t*)&bs[n*HST + k0 + 8];
            }
            #pragma unroll
            for (int mt = 0; mt < 2; mt++)
                #pragma unroll
                for (int nt = 0; nt < 8; nt++)
                    mma_f16(G.a[mt][nt], a[mt], b[nt][0], b[nt][1]);
        }
        __syncthreads();
        if (c + 2 < NCH) { loadA(c+2, buf); loadB(c+2, buf); }
        cp_commit();
    }
}

// Fused QKV GEMM: BT = [Wq^T; Wk^T; Wv^T] (2304 x 768), grid (18, 98).
// Output scattered head-major into Cq/Ck/Cv.
__global__ void __launch_bounds__(256, 2)
mma_gemm_qkv(const __half* __restrict__ A, const __half* __restrict__ BT,
             const float* __restrict__ bq, const float* __restrict__ bk,
             const float* __restrict__ bv,
             float* __restrict__ Cq, float* __restrict__ Ck, float* __restrict__ Cv)
{
    extern __shared__ __half smh[];
    const int bx = blockIdx.x, by = blockIdx.y;
    const int mat = bx / 6;                  // 0=Q 1=K 2=V (BN*6 == GD)
    const float* bias = (mat == 0) ? bq : (mat == 1) ? bk : bv;
    float* C = (mat == 0) ? Cq : (mat == 1) ? Ck : Cv;
    const int bxm = bx - mat*6;

    GemmAcc G;
    gemm_mainloop(A + (size_t)(by*BM)*GD, BT + (size_t)(bx*BN)*GD,
                  smh, smh + 2*HASZ, G);

    const int tid = threadIdx.x, wid = tid >> 5, lane = tid & 31;
    const int wm = wid & 3, wn = wid >> 2;
    const int lr = lane >> 2, lq = lane & 3;

    #pragma unroll
    for (int mt = 0; mt < 2; mt++) {
        #pragma unroll
        for (int h8 = 0; h8 < 2; h8++) {
            const int row = by*BM + wm*32 + mt*16 + h8*8 + lr;
            const int bb = row / GN, nn = row % GN;
            #pragma unroll
            for (int nt = 0; nt < 8; nt++) {
                const int col = bxm*BN + wn*64 + nt*8 + 2*lq;
                float2 v;
                v.x = G.a[mt][nt][h8*2+0] + bias[col];
                v.y = G.a[mt][nt][h8*2+1] + bias[col+1];
                const int h = col >> 6, hd = col & 63;
                *(float2*)(C + (((size_t)bb*GH + h)*GN + nn)*GHD + hd) = v;
            }
        }
    }
}

// Output GEMM: plain [M,768] output + bias
__global__ void __launch_bounds__(256, 2)
mma_gemm_out(const __half* __restrict__ A, const __half* __restrict__ BT,
             const float* __restrict__ bias, float* __restrict__ C)
{
    extern __shared__ __half smh[];
    const int bx = blockIdx.x, by = blockIdx.y;

    GemmAcc G;
    gemm_mainloop(A + (size_t)(by*BM)*GD, BT + (size_t)(bx*BN)*GD,
                  smh, smh + 2*HASZ, G);

    const int tid = threadIdx.x, wid = tid >> 5, lane = tid & 31;
    const int wm = wid & 3, wn = wid >> 2;
    const int lr = lane >> 2, lq = lane & 3;

    #pragma unroll
    for (int mt = 0; mt < 2; mt++) {
        #pragma unroll
        for (int h8 = 0; h8 < 2; h8++) {
            const int row = by*BM + wm*32 + mt*16 + h8*8 + lr;
            #pragma unroll
            for (int nt = 0; nt < 8; nt++) {
                const int col = bx*BN + wn*64 + nt*8 + 2*lq;
                float2 v;
                v.x = G.a[mt][nt][h8*2+0] + bias[col];
                v.y = G.a[mt][nt][h8*2+1] + bias[col+1];
                *(float2*)(C + (size_t)row*GD + col) = v;
            }
        }
    }
}

// ---------------- Attention core: fp16 K/V smem, occupancy 2 ---------------
// One CTA per (b,h), 512 thr / 16 warps, 4 query rows per warp-group-iter.
// smem:
//   K2h [32][200] half2 : K2h[dp][j] = (K[j][2dp], K[j][2dp+1])   25600 B
//   Vh2 [196][32] half2 : Vh2[j][dp] = (V[j][2dp], V[j][2dp+1])   25088 B
//   Ps  [16][4*196] f32 : per-warp P scratch; front doubles as Q stage 50176 B
#define KJS 200
#define ATT_SMEM_BYTES (32*KJS*4 + GN*32*4 + 16*4*GN*4)   // 100864 B

__global__ void __launch_bounds__(512, 2)
attn_kernel(const float* __restrict__ Q, const float* __restrict__ K,
            const float* __restrict__ V, const float* __restrict__ Wsig,
            const float* __restrict__ bsigp, const float* __restrict__ tempp,
            __half* __restrict__ CTX)
{
    extern __shared__ float smf[];
    __half2* K2h = (__half2*)smf;                    // [32][200]
    __half2* Vh2 = (__half2*)(smf + 32*KJS);         // [196][32]
    float*   Ps  = smf + 32*KJS + GN*32;             // [16][784]

    const int bh = blockIdx.x;
    const int b = bh / GH, h = bh % GH;
    const float* Qg = Q + (size_t)bh * GN * GHD;
    const float* Kg = K + (size_t)bh * GN * GHD;
    const float* Vg = V + (size_t)bh * GN * GHD;

    const int tid = threadIdx.x;

    // load K (dim-pair-major, fp16) and V (row-major dim-pairs, fp16)
    for (int idx = tid; idx < GN*32; idx += 512) {
        int j = idx >> 5, dp = idx & 31;
        float2 kf = *(const float2*)&Kg[j*GHD + 2*dp];
        float2 vf = *(const float2*)&Vg[j*GHD + 2*dp];
        K2h[dp*KJS + j] = __floats2half2_rn(kf.x, kf.y);
        Vh2[j*32 + dp]  = __floats2half2_rn(vf.x, vf.y);
    }
    // zero K pad columns j=196..199 (dot loop overreads them)
    for (int idx = tid; idx < 32*4; idx += 512) {
        int dp = idx >> 2, j = GN + (idx & 3);
        K2h[dp*KJS + j] = __floats2half2_rn(0.f, 0.f);
    }
    __syncthreads();

    const int wid = tid >> 5, lane = tid & 31;
    const float temperature = tempp[0];
    const float bsg = bsigp[0];
    const float2 ws2 = *(const float2*)&Wsig[2*lane];

    float* Pw = Ps + wid * 784;          // this warp's scratch (Q stage, then P)
    float2* Qst = (float2*)Pw;           // [4][32] float2 view

    for (int p = wid; p < GN/4; p += 16) {
        const int i0 = p * 4;

        // ---- stage Q rows (fp32) into warp scratch ----
        #pragma unroll
        for (int r = 0; r < 4; r++)
            Qst[r*32 + lane] = *(const float2*)&Qg[(i0 + r)*GHD + 2*lane];
        __syncwarp();

        // ---- per-row sigma -> denom ----
        float denom[4];
        #pragma unroll
        for (int r = 0; r < 4; r++) {
            float2 q2 = Qst[r*32 + lane];
            float part = q2.x*ws2.x + q2.y*ws2.y;
            #pragma unroll
            for (int o = 16; o > 0; o >>= 1)
                part += __shfl_xor_sync(0xffffffffu, part, o);
            float x = part + bsg;
            float sp = (x > 20.f) ? x : log1pf(expf(x));
            float sig = sp + 1e-3f;
            float st = sig * temperature;
            denom[r] = 2.f * st * st;
        }

        // ---- raw scores: 4 rows x 7 keys per lane ----
        float acc[4][7];
        #pragma unroll
        for (int r = 0; r < 4; r++)
            #pragma unroll
            for (int t = 0; t < 7; t++) acc[r][t] = 0.f;

        #pragma unroll 4
        for (int dp = 0; dp < 32; dp++) {
            float2 q0 = Qst[0*32 + dp];
            float2 q1 = Qst[1*32 + dp];
            float2 q2 = Qst[2*32 + dp];
            float2 q3 = Qst[3*32 + dp];
            const __half2* kr = K2h + dp*KJS + lane;
            #pragma unroll
            for (int t = 0; t < 7; t++) {
                float2 kv = __half22float2(kr[32*t]);
                acc[0][t] += q0.x*kv.x + q0.y*kv.y;
                acc[1][t] += q1.x*kv.x + q1.y*kv.y;
                acc[2][t] += q2.x*kv.x + q2.y*kv.y;
                acc[3][t] += q3.x*kv.x + q3.y*kv.y;
            }
        }

        // ---- gaussian mask * score, softmax, write P over Q stage ----
        // (the full-mask shuffles below guarantee all lanes finished the
        //  dot loop before any P write aliases the Q stage)
        #pragma unroll
        for (int r = 0; r < 4; r++) {
            const int i = i0 + r;
            const int iy = i / GSIDE, ix = i % GSIDE;
            const float inv_denom = -1.f / denom[r];
            float mx = -1e30f;
            #pragma unroll
            for (int t = 0; t < 7; t++) {
                int j = lane + 32*t;
                if (j < GN) {
                    int jy = j / GSIDE, jx = j % GSIDE;
                    float dy = (float)(iy - jy), dx = (float)(ix - jx);
                    float d2 = dy*dy + dx*dx;
                    float val = __expf(d2 * inv_denom) * (acc[r][t] * 0.125f);
                    acc[r][t] = val;
                    mx = fmaxf(mx, val);
                } else {
                    acc[r][t] = -1e30f;
                }
            }
            #pragma unroll
            for (int o = 16; o > 0; o >>= 1)
                mx = fmaxf(mx, __shfl_xor_sync(0xffffffffu, mx, o));
            float sum = 0.f;
            #pragma unroll
            for (int t = 0; t < 7; t++) {
                int j = lane + 32*t;
                if (j < GN) {
                    float e = __expf(acc[r][t] - mx);
                    acc[r][t] = e;
                    sum += e;
                }
            }
            #pragma unroll
            for (int o = 16; o > 0; o >>= 1)
                sum += __shfl_xor_sync(0xffffffffu, sum, o);
            float inv = 1.f / sum;
            float* prow = Pw + r*GN;
            #pragma unroll
            for (int t = 0; t < 7; t++) {
                int j = lane + 32*t;
                if (j < GN) prow[j] = acc[r][t] * inv;
            }
        }
        __syncwarp();

        // ---- ctx = P @ V : lane owns dims (2*lane, 2*lane+1) ----
        float2 ctx[4];
        #pragma unroll
        for (int r = 0; r < 4; r++) ctx[r] = make_float2(0.f, 0.f);

        const float* p0 = Pw;
        const float* p1 = Pw + GN;
        const float* p2 = Pw + 2*GN;
        const float* p3 = Pw + 3*GN;
        #pragma unroll 7
        for (int j = 0; j < GN; j += 4) {
            float4 w0 = *(const float4*)(p0 + j);
            float4 w1 = *(const float4*)(p1 + j);
            float4 w2 = *(const float4*)(p2 + j);
            float4 w3 = *(const float4*)(p3 + j);
            #pragma unroll
            for (int jj = 0; jj < 4; jj++) {
                float2 v = __half22float2(Vh2[(j + jj)*32 + lane]);
                float a0 = jj==0 ? w0.x : jj==1 ? w0.y : jj==2 ? w0.z : w0.w;
                float a1 = jj==0 ? w1.x : jj==1 ? w1.y : jj==2 ? w1.z : w1.w;
                float a2 = jj==0 ? w2.x : jj==1 ? w2.y : jj==2 ? w2.z : w2.w;
                float a3 = jj==0 ? w3.x : jj==1 ? w3.y : jj==2 ? w3.z : w3.w;
                ctx[0].x += a0*v.x; ctx[0].y += a0*v.y;
                ctx[1].x += a1*v.x; ctx[1].y += a1*v.y;
                ctx[2].x += a2*v.x; ctx[2].y += a2*v.y;
                ctx[3].x += a3*v.x; ctx[3].y += a3*v.y;
            }
        }

        // ---- store ctx fp16 at dims (2*lane, 2*lane+1) ----
        {
            __half2* C2 = (__half2*)(CTX + ((size_t)(b*GN + i0))*GD + h*GHD);
            #pragma unroll
            for (int r = 0; r < 4; r++)
                C2[r*(GD/2) + lane] = __floats2half2_rn(ctx[r].x, ctx[r].y);
        }
        __syncwarp();   // scratch reused next group
    }
}

// ---------------- launch ----------------------------------------------------
extern "C" void kernel_launch(void* const* d_in, const int* in_sizes, int n_in,
                              void* d_out, int out_size)
{
    const float* hs   = (const float*)d_in[0];
    const float* temp = (const float*)d_in[1];
    const float* Wq   = (const float*)d_in[2];
    const float* bq   = (const float*)d_in[3];
    const float* Wk   = (const float*)d_in[4];
    const float* bk   = (const float*)d_in[5];
    const float* Wv   = (const float*)d_in[6];
    const float* bv   = (const float*)d_in[7];
    const float* Wo   = (const float*)d_in[8];
    const float* bo   = (const float*)d_in[9];
    const float* Wsig = (const float*)d_in[10];
    const float* bsig = (const float*)d_in[11];
    float* out = (float*)d_out;

    float *gq, *gk, *gv;
    __half *ghs, *gwt, *gctx;
    cudaGetSymbolAddress((void**)&gq,   g_q);
    cudaGetSymbolAddress((void**)&gk,   g_k);
    cudaGetSymbolAddress((void**)&gv,   g_v);
    cudaGetSymbolAddress((void**)&ghs,  g_hs_h);
    cudaGetSymbolAddress((void**)&gwt,  g_wt_h);
    cudaGetSymbolAddress((void**)&gctx, g_ctx_h);

    cudaFuncSetAttribute(attn_kernel,
                         cudaFuncAttributeMaxDynamicSharedMemorySize,
                         ATT_SMEM_BYTES);
    cudaFuncSetAttribute(mma_gemm_qkv,
                         cudaFuncAttributeMaxDynamicSharedMemorySize,
                         GEMM_SMEM);
    cudaFuncSetAttribute(mma_gemm_out,
                         cudaFuncAttributeMaxDynamicSharedMemorySize,
                         GEMM_SMEM);

    __half* wto = gwt + 3ull*GD*GD;

    const int nhs4 = GM*GD/4;
    conv_f2h<<<(nhs4 + 255)/256, 256>>>(hs, ghs, nhs4);
    dim3 tb(32, 8), tg(GD/32, GD/32, 4);
    transpose_f2h4<<<tg, tb>>>(Wq, Wk, Wv, Wo, gwt);

    dim3 gqkv(3*GD/BN, GM/BM);   // (18, 98)
    mma_gemm_qkv<<<gqkv, 256, GEMM_SMEM>>>(ghs, gwt, bq, bk, bv, gq, gk, gv);
    attn_kernel<<<GB*GH, 512, ATT_SMEM_BYTES>>>(gq, gk, gv, Wsig, bsig, temp, gctx);
    dim3 gout(GD/BN, GM/BM);     // (6, 98)
    mma_gemm_out<<<gout, 256, GEMM_SMEM>>>(gctx, wto, bo, out);
}

// round 8
// speedup vs baseline: 1.6721x; 1.5374x over previous
#include <cuda_runtime.h>
#include <cuda_fp16.h>
#include <cstdint>

// Problem constants
#define GB 64
#define GN 196
#define GD 768
#define GH 12
#define GHD 64
#define GSIDE 14
#define GM (GB*GN)   // 12544

// Scratch (device globals: allocation-free rule)
__device__ __align__(16) __half g_q_h[GB*GH*GN*GHD];     // fp16 Q head-major
__device__ __align__(16) __half g_k_h[GB*GH*GN*GHD];     // fp16 K head-major
__device__ __align__(16) __half g_vt_h[GB*GH*GHD*GN];    // fp16 V transposed [head][64][196]
__device__ __align__(16) __half g_hs_h[(size_t)GM*GD];   // fp16 hidden states
__device__ __align__(16) __half g_wt_h[4*GD*GD];         // fp16 transposed weights [N][K]
__device__ __align__(16) __half g_ctx_h[(size_t)GM*GD];  // fp16 ctx

// ============================ helpers =======================================
__device__ __forceinline__ uint32_t smem_u32(const void* p) {
    uint32_t a;
    asm("{ .reg .u64 t; cvta.to.shared.u64 t, %1; cvt.u32.u64 %0, t; }" : "=r"(a) : "l"(p));
    return a;
}
__device__ __forceinline__ void cp16(uint32_t s, const void* g) {
    asm volatile("cp.async.cg.shared.global [%0], [%1], 16;" :: "r"(s), "l"(g));
}
__device__ __forceinline__ void cp_commit() { asm volatile("cp.async.commit_group;" ::: "memory"); }
__device__ __forceinline__ void cp_wait1()  { asm volatile("cp.async.wait_group 1;"  ::: "memory"); }

__device__ __forceinline__ void mma_f16(float* c, const uint32_t* a, uint32_t b0, uint32_t b1) {
    asm volatile(
        "mma.sync.aligned.m16n8k16.row.col.f32.f16.f16.f32 "
        "{%0,%1,%2,%3}, {%4,%5,%6,%7}, {%8,%9}, {%0,%1,%2,%3};"
        : "+f"(c[0]), "+f"(c[1]), "+f"(c[2]), "+f"(c[3])
        : "r"(a[0]), "r"(a[1]), "r"(a[2]), "r"(a[3]), "r"(b0), "r"(b1));
}
__device__ __forceinline__ uint32_t h2_bits(float x, float y) {
    __half2 h = __floats2half2_rn(x, y);
    return *(uint32_t*)&h;
}

// ===================== conversion pre-passes ================================
__global__ void conv_f2h(const float* __restrict__ s, __half* __restrict__ d, int n4) {
    int i = blockIdx.x * blockDim.x + threadIdx.x;
    if (i < n4) {
        float4 v = ((const float4*)s)[i];
        __half2 lo = __floats2half2_rn(v.x, v.y);
        __half2 hi = __floats2half2_rn(v.z, v.w);
        uint2 o;
        o.x = *(uint32_t*)&lo;
        o.y = *(uint32_t*)&hi;
        ((uint2*)d)[i] = o;
    }
}

// 4 transposes in one launch: z selects the matrix
__global__ void transpose_f2h4(const float* __restrict__ W0, const float* __restrict__ W1,
                               const float* __restrict__ W2, const float* __restrict__ W3,
                               __half* __restrict__ T)
{
    __shared__ float tile[32][33];
    const float* S = (blockIdx.z == 0) ? W0 : (blockIdx.z == 1) ? W1 :
                     (blockIdx.z == 2) ? W2 : W3;
    __half* D = T + (size_t)blockIdx.z * GD * GD;
    int tx = threadIdx.x, ty = threadIdx.y;
    int x = blockIdx.x * 32 + tx;
    int y = blockIdx.y * 32 + ty;
    #pragma unroll
    for (int j = 0; j < 32; j += 8)
        tile[ty + j][tx] = S[(size_t)(y + j) * GD + x];
    __syncthreads();
    int x2 = blockIdx.y * 32 + tx;
    int y2 = blockIdx.x * 32 + ty;
    #pragma unroll
    for (int j = 0; j < 32; j += 8)
        D[(size_t)(y2 + j) * GD + x2] = __float2half(tile[tx][ty + j]);
}

// ===================== fp16 mma.sync GEMM core ==============================
#define BM 128
#define BN 128
#define HBK 64
#define HST 72
#define HASZ (BM*HST)
#define HBSZ (BN*HST)
#define GEMM_SMEM ((2*HASZ + 2*HBSZ)*2)   // 73728 B
#define NCH (GD/HBK)                      // 12

struct GemmAcc { float a[2][8][4]; };

__device__ __forceinline__ void gemm_mainloop(
    const __half* __restrict__ Ag, const __half* __restrict__ Bg,
    __half* As, __half* Bs, GemmAcc& G)
{
    const uint32_t abase = smem_u32(As);
    const uint32_t bbase = smem_u32(Bs);
    const int tid = threadIdx.x;

    auto loadA = [&](int c, int buf) {
        const __half* ag = Ag + c*HBK;
        const uint32_t dst = abase + buf*HASZ*2;
        #pragma unroll
        for (int it = 0; it < 4; it++) {
            int idx = tid + 256*it;
            int m = idx >> 3, k8 = idx & 7;
            cp16(dst + (m*HST + k8*8)*2, ag + (size_t)m*GD + k8*8);
        }
    };
    auto loadB = [&](int c, int buf) {
        const __half* bg = Bg + c*HBK;
        const uint32_t dst = bbase + buf*HBSZ*2;
        #pragma unroll
        for (int it = 0; it < 4; it++) {
            int idx = tid + 256*it;
            int n = idx >> 3, k8 = idx & 7;
            cp16(dst + (n*HST + k8*8)*2, bg + (size_t)n*GD + k8*8);
        }
    };

    loadA(0, 0); loadB(0, 0); cp_commit();
    loadA(1, 1); loadB(1, 1); cp_commit();

    const int wid = tid >> 5, lane = tid & 31;
    const int wm = wid & 3, wn = wid >> 2;
    const int lr = lane >> 2, lq = lane & 3;

    #pragma unroll
    for (int i = 0; i < 2; i++)
        #pragma unroll
        for (int j = 0; j < 8; j++)
            #pragma unroll
            for (int k = 0; k < 4; k++) G.a[i][j][k] = 0.f;

    for (int c = 0; c < NCH; c++) {
        cp_wait1();
        __syncthreads();
        const int buf = c & 1;
        const __half* as = As + buf*HASZ;
        const __half* bs = Bs + buf*HBSZ;

        #pragma unroll
        for (int s = 0; s < 4; s++) {
            const int k0 = s*16 + 2*lq;
            uint32_t a[2][4], b[8][2];
            #pragma unroll
            for (int mt = 0; mt < 2; mt++) {
                const int r = wm*32 + mt*16 + lr;
                a[mt][0] = *(const uint32_t*)&as[r*HST + k0];
                a[mt][1] = *(const uint32_t*)&as[(r+8)*HST + k0];
                a[mt][2] = *(const uint32_t*)&as[r*HST + k0 + 8];
                a[mt][3] = *(const uint32_t*)&as[(r+8)*HST + k0 + 8];
            }
            #pragma unroll
            for (int nt = 0; nt < 8; nt++) {
                const int n = wn*64 + nt*8 + lr;
                b[nt][0] = *(const uint32_t*)&bs[n*HST + k0];
                b[nt][1] = *(const uint32_t*)&bs[n*HST + k0 + 8];
            }
            #pragma unroll
            for (int mt = 0; mt < 2; mt++)
                #pragma unroll
                for (int nt = 0; nt < 8; nt++)
                    mma_f16(G.a[mt][nt], a[mt], b[nt][0], b[nt][1]);
        }
        __syncthreads();
        if (c + 2 < NCH) { loadA(c+2, buf); loadB(c+2, buf); }
        cp_commit();
    }
}

// Fused QKV GEMM. Q,K written fp16 head-major; V written fp16 TRANSPOSED.
__global__ void __launch_bounds__(256, 2)
mma_gemm_qkv(const __half* __restrict__ A, const __half* __restrict__ BT,
             const float* __restrict__ bq, const float* __restrict__ bk,
             const float* __restrict__ bv,
             __half* __restrict__ Cq, __half* __restrict__ Ck, __half* __restrict__ Cvt)
{
    extern __shared__ __half smh[];
    const int bx = blockIdx.x, by = blockIdx.y;
    const int mat = bx / 6;                  // 0=Q 1=K 2=V
    const float* bias = (mat == 0) ? bq : (mat == 1) ? bk : bv;
    const int bxm = bx - mat*6;

    GemmAcc G;
    gemm_mainloop(A + (size_t)(by*BM)*GD, BT + (size_t)(bx*BN)*GD,
                  smh, smh + 2*HASZ, G);

    const int tid = threadIdx.x, wid = tid >> 5, lane = tid & 31;
    const int wm = wid & 3, wn = wid >> 2;
    const int lr = lane >> 2, lq = lane & 3;

    #pragma unroll
    for (int mt = 0; mt < 2; mt++) {
        #pragma unroll
        for (int h8 = 0; h8 < 2; h8++) {
            const int row = by*BM + wm*32 + mt*16 + h8*8 + lr;
            const int bb = row / GN, nn = row % GN;
            #pragma unroll
            for (int nt = 0; nt < 8; nt++) {
                const int col = bxm*BN + wn*64 + nt*8 + 2*lq;
                float vx = G.a[mt][nt][h8*2+0] + bias[col];
                float vy = G.a[mt][nt][h8*2+1] + bias[col+1];
                const int h = col >> 6, hd = col & 63;
                if (mat == 2) {
                    __half* vt = Cvt + (((size_t)bb*GH + h)*GHD)*GN;
                    vt[(size_t)hd*GN + nn]     = __float2half(vx);
                    vt[(size_t)(hd+1)*GN + nn] = __float2half(vy);
                } else {
                    __half* C = (mat == 0) ? Cq : Ck;
                    uint32_t bits = h2_bits(vx, vy);
                    *(uint32_t*)(C + (((size_t)bb*GH + h)*GN + nn)*GHD + hd) = bits;
                }
            }
        }
    }
}

// Output GEMM: fp32 output + bias
__global__ void __launch_bounds__(256, 2)
mma_gemm_out(const __half* __restrict__ A, const __half* __restrict__ BT,
             const float* __restrict__ bias, float* __restrict__ C)
{
    extern __shared__ __half smh[];
    const int bx = blockIdx.x, by = blockIdx.y;

    GemmAcc G;
    gemm_mainloop(A + (size_t)(by*BM)*GD, BT + (size_t)(bx*BN)*GD,
                  smh, smh + 2*HASZ, G);

    const int tid = threadIdx.x, wid = tid >> 5, lane = tid & 31;
    const int wm = wid & 3, wn = wid >> 2;
    const int lr = lane >> 2, lq = lane & 3;

    #pragma unroll
    for (int mt = 0; mt < 2; mt++) {
        #pragma unroll
        for (int h8 = 0; h8 < 2; h8++) {
            const int row = by*BM + wm*32 + mt*16 + h8*8 + lr;
            #pragma unroll
            for (int nt = 0; nt < 8; nt++) {
                const int col = bx*BN + wn*64 + nt*8 + 2*lq;
                float2 v;
                v.x = G.a[mt][nt][h8*2+0] + bias[col];
                v.y = G.a[mt][nt][h8*2+1] + bias[col+1];
                *(float2*)(C + (size_t)row*GD + col) = v;
            }
        }
    }
}

// ============ FlashAttention-style mma attention ============================
// CTA = 128 thr / 4 warps, handles 64 query rows of one (b,h).
// Grid = 768 heads x 4 row-chunks. Warp w: rows [chunk*64 + w*16, +16).
// smem: Ks [200][72] fp16 (28800B), Vt [64][216] fp16 (27648B), invden[64] f32.
// S = Q K^T via m16n8k16 (A=Q regs, B=K smem); online softmax in regs;
// P c-frags -> half2 -> A-frags of P*V mma (B=V^T smem). All accum fp32.
#define AKST 72
#define AVST 216
#define ATT_SMEM (200*AKST*2 + 64*AVST*2 + 64*4)   // 56960 B

__global__ void __launch_bounds__(128)
attn_flash(const __half* __restrict__ Qh, const __half* __restrict__ Kh,
           const __half* __restrict__ Vth, const float* __restrict__ Wsig,
           const float* __restrict__ bsigp, const float* __restrict__ tempp,
           __half* __restrict__ CTX)
{
    extern __shared__ __half smh[];
    __half* Ks = smh;                       // [200][72]
    __half* Vt = smh + 200*AKST;            // [64][216]
    float* invden = (float*)(smh + 200*AKST + 64*AVST);  // [64]

    const int bh = blockIdx.x >> 2, chunk = blockIdx.x & 3;
    const __half* Qg  = Qh  + (size_t)bh * GN * GHD;
    const __half* Kg  = Kh  + (size_t)bh * GN * GHD;
    const __half* Vtg = Vth + (size_t)bh * GHD * GN;

    const int tid = threadIdx.x;

    // ---- prologue: K [196][64] -> Ks [200][72]; Vt [64][196] -> [64][216] ----
    for (int idx = tid; idx < GN*32; idx += 128) {
        int j = idx >> 5, dp = idx & 31;
        *(uint32_t*)&Ks[j*AKST + 2*dp] = *(const uint32_t*)&Kg[j*GHD + 2*dp];
    }
    for (int idx = tid; idx < GHD*98; idx += 128) {
        int d = idx / 98, jp = idx - d*98;
        *(uint32_t*)&Vt[d*AVST + 2*jp] = *(const uint32_t*)&Vtg[d*GN + 2*jp];
    }
    // zero V pad cols j in [196,216) (P=0 x junk-NaN would poison HMMA)
    for (int idx = tid; idx < GHD*10; idx += 128) {
        int d = idx / 10, c = idx - d*10;
        *(uint32_t*)&Vt[d*AVST + GN + 2*c] = 0u;
    }
    // ---- sigma -> -1/denom per local row ----
    if (tid < 64) {
        int r = chunk*64 + tid;
        if (r > GN-1) r = GN-1;
        const __half* qr = Qg + r*GHD;
        float acc = 0.f;
        #pragma unroll 8
        for (int dp = 0; dp < 32; dp++) {
            float2 q = __half22float2(*(const __half2*)&qr[2*dp]);
            float2 w = *(const float2*)&Wsig[2*dp];
            acc += q.x*w.x + q.y*w.y;
        }
        float x = acc + bsigp[0];
        float sp = (x > 20.f) ? x : log1pf(expf(x));
        float sg = (sp + 1e-3f) * tempp[0];
        invden[tid] = -1.f / (2.f*sg*sg);
    }
    __syncthreads();

    const int w = tid >> 5, lane = tid & 31;
    const int m0 = chunk*64 + w*16;
    if (m0 >= GN) return;    // warp-uniform; no further CTA syncs

    const int lr = lane >> 2, lq = lane & 3;
    const int row_lo = m0 + lr, row_hi = row_lo + 8;
    const int rlo = (row_lo > GN-1) ? GN-1 : row_lo;
    const int rhi = (row_hi > GN-1) ? GN-1 : row_hi;
    const float ivd_lo = invden[w*16 + lr];
    const float ivd_hi = invden[w*16 + lr + 8];
    const int iy_lo = (rlo*2341) >> 15, ix_lo = rlo - GSIDE*iy_lo;
    const int iy_hi = (rhi*2341) >> 15, ix_hi = rhi - GSIDE*iy_hi;

    // ---- Q A-fragments: 4 k-steps over 64 dims ----
    uint32_t qa[4][4];
    {
        const __half* qlo = Qg + rlo*GHD + 2*lq;
        const __half* qhi = Qg + rhi*GHD + 2*lq;
        #pragma unroll
        for (int ks = 0; ks < 4; ks++) {
            qa[ks][0] = *(const uint32_t*)&qlo[16*ks];
            qa[ks][1] = *(const uint32_t*)&qhi[16*ks];
            qa[ks][2] = *(const uint32_t*)&qlo[16*ks + 8];
            qa[ks][3] = *(const uint32_t*)&qhi[16*ks + 8];
        }
    }

    float ctx[8][4];
    #pragma unroll
    for (int nt = 0; nt < 8; nt++)
        #pragma unroll
        for (int c = 0; c < 4; c++) ctx[nt][c] = 0.f;
    float m_lo = -1e30f, m_hi = -1e30f, l_lo = 0.f, l_hi = 0.f;

    #pragma unroll 1
    for (int pr = 0; pr < 13; pr++) {
        // ---- S for n-tile pair (2pr, 2pr+1): cols [16pr, 16pr+16) ----
        float sa[4] = {0.f,0.f,0.f,0.f}, sb[4] = {0.f,0.f,0.f,0.f};
        const __half* ka = Ks + (pr*16 + lr)*AKST + 2*lq;
        #pragma unroll
        for (int ks = 0; ks < 4; ks++)
            mma_f16(sa, qa[ks], *(const uint32_t*)&ka[16*ks],
                                *(const uint32_t*)&ka[16*ks + 8]);
        if (pr < 12) {
            const __half* kb = ka + 8*AKST;
            #pragma unroll
            for (int ks = 0; ks < 4; ks++)
                mma_f16(sb, qa[ks], *(const uint32_t*)&kb[16*ks],
                                    *(const uint32_t*)&kb[16*ks + 8]);
        }

        // ---- gaussian-masked logits ----
        const int ja = pr*16 + 2*lq, jb = ja + 8;
        float lg[8];
        #pragma unroll
        for (int e = 0; e < 8; e++) {
            const int j = ((e & 4) ? jb : ja) + (e & 1);
            const float s = (e & 4) ? sb[e & 3] : sa[e & 3];
            const bool hiRow = (e & 2);
            if (j < GN) {
                int jy = (j*2341) >> 15, jx = j - GSIDE*jy;
                int dy = (hiRow ? iy_hi : iy_lo) - jy;
                int dx = (hiRow ? ix_hi : ix_lo) - jx;
                float d2 = (float)(dy*dy + dx*dx);
                lg[e] = __expf(d2 * (hiRow ? ivd_hi : ivd_lo)) * (s * 0.125f);
            } else {
                lg[e] = -1e30f;
            }
        }

        // ---- online softmax update (quad = one row) ----
        float ml_lo = fmaxf(fmaxf(lg[0], lg[1]), fmaxf(lg[4], lg[5]));
        float ml_hi = fmaxf(fmaxf(lg[2], lg[3]), fmaxf(lg[6], lg[7]));
        ml_lo = fmaxf(ml_lo, __shfl_xor_sync(0xffffffffu, ml_lo, 1));
        ml_lo = fmaxf(ml_lo, __shfl_xor_sync(0xffffffffu, ml_lo, 2));
        ml_hi = fmaxf(ml_hi, __shfl_xor_sync(0xffffffffu, ml_hi, 1));
        ml_hi = fmaxf(ml_hi, __shfl_xor_sync(0xffffffffu, ml_hi, 2));
        const float mn_lo = fmaxf(m_lo, ml_lo);
        const float mn_hi = fmaxf(m_hi, ml_hi);
        const float sc_lo = __expf(m_lo - mn_lo);
        const float sc_hi = __expf(m_hi - mn_hi);
        m_lo = mn_lo; m_hi = mn_hi;

        const float p0 = __expf(lg[0] - mn_lo), p1 = __expf(lg[1] - mn_lo);
        const float p2 = __expf(lg[2] - mn_hi), p3 = __expf(lg[3] - mn_hi);
        const float p4 = __expf(lg[4] - mn_lo), p5 = __expf(lg[5] - mn_lo);
        const float p6 = __expf(lg[6] - mn_hi), p7 = __expf(lg[7] - mn_hi);
        l_lo = l_lo*sc_lo + (p0 + p1 + p4 + p5);
        l_hi = l_hi*sc_hi + (p2 + p3 + p6 + p7);

        uint32_t pa[4];
        pa[0] = h2_bits(p0, p1);
        pa[1] = h2_bits(p2, p3);
        pa[2] = h2_bits(p4, p5);
        pa[3] = h2_bits(p6, p7);

        // ---- rescale ctx + P*V k-step ----
        const __half* vbase = Vt + pr*16 + 2*lq;
        #pragma unroll
        for (int nt = 0; nt < 8; nt++) {
            ctx[nt][0] *= sc_lo; ctx[nt][1] *= sc_lo;
            ctx[nt][2] *= sc_hi; ctx[nt][3] *= sc_hi;
            const __half* vp = vbase + (nt*8 + lr)*AVST;
            mma_f16(ctx[nt], pa, *(const uint32_t*)&vp[0],
                                 *(const uint32_t*)&vp[8]);
        }
    }

    // ---- finalize ----
    l_lo += __shfl_xor_sync(0xffffffffu, l_lo, 1);
    l_lo += __shfl_xor_sync(0xffffffffu, l_lo, 2);
    l_hi += __shfl_xor_sync(0xffffffffu, l_hi, 1);
    l_hi += __shfl_xor_sync(0xffffffffu, l_hi, 2);
    const float il_lo = 1.f / l_lo, il_hi = 1.f / l_hi;

    const int b = bh / GH, h = bh % GH;
    __half* out_lo = CTX + ((size_t)(b*GN + row_lo))*GD + h*GHD + 2*lq;
    __half* out_hi = CTX + ((size_t)(b*GN + row_hi))*GD + h*GHD + 2*lq;
    #pragma unroll
    for (int nt = 0; nt < 8; nt++) {
        if (row_lo < GN)
            *(uint32_t*)&out_lo[nt*8] = h2_bits(ctx[nt][0]*il_lo, ctx[nt][1]*il_lo);
        if (row_hi < GN)
            *(uint32_t*)&out_hi[nt*8] = h2_bits(ctx[nt][2]*il_hi, ctx[nt][3]*il_hi);
    }
}

// ---------------- launch ----------------------------------------------------
extern "C" void kernel_launch(void* const* d_in, const int* in_sizes, int n_in,
                              void* d_out, int out_size)
{
    const float* hs   = (const float*)d_in[0];
    const float* temp = (const float*)d_in[1];
    const float* Wq   = (const float*)d_in[2];
    const float* bq   = (const float*)d_in[3];
    const float* Wk   = (const float*)d_in[4];
    const float* bk   = (const float*)d_in[5];
    const float* Wv   = (const float*)d_in[6];
    const float* bv   = (const float*)d_in[7];
    const float* Wo   = (const float*)d_in[8];
    const float* bo   = (const float*)d_in[9];
    const float* Wsig = (const float*)d_in[10];
    const float* bsig = (const float*)d_in[11];
    float* out = (float*)d_out;

    __half *gq, *gk, *gvt, *ghs, *gwt, *gctx;
    cudaGetSymbolAddress((void**)&gq,   g_q_h);
    cudaGetSymbolAddress((void**)&gk,   g_k_h);
    cudaGetSymbolAddress((void**)&gvt,  g_vt_h);
    cudaGetSymbolAddress((void**)&ghs,  g_hs_h);
    cudaGetSymbolAddress((void**)&gwt,  g_wt_h);
    cudaGetSymbolAddress((void**)&gctx, g_ctx_h);

    cudaFuncSetAttribute(attn_flash,
                         cudaFuncAttributeMaxDynamicSharedMemorySize, ATT_SMEM);
    cudaFuncSetAttribute(mma_gemm_qkv,
                         cudaFuncAttributeMaxDynamicSharedMemorySize, GEMM_SMEM);
    cudaFuncSetAttribute(mma_gemm_out,
                         cudaFuncAttributeMaxDynamicSharedMemorySize, GEMM_SMEM);

    __half* wto = gwt + 3ull*GD*GD;

    const int nhs4 = GM*GD/4;
    conv_f2h<<<(nhs4 + 255)/256, 256>>>(hs, ghs, nhs4);
    dim3 tb(32, 8), tg(GD/32, GD/32, 4);
    transpose_f2h4<<<tg, tb>>>(Wq, Wk, Wv, Wo, gwt);

    dim3 gqkv(3*GD/BN, GM/BM);   // (18, 98)
    mma_gemm_qkv<<<gqkv, 256, GEMM_SMEM>>>(ghs, gwt, bq, bk, bv, gq, gk, gvt);
    attn_flash<<<GB*GH*4, 128, ATT_SMEM>>>(gq, gk, gvt, Wsig, bsig, temp, gctx);
    dim3 gout(GD/BN, GM/BM);     // (6, 98)
    mma_gemm_out<<<gout, 256, GEMM_SMEM>>>(gctx, wto, bo, out);
}

// round 9
// speedup vs baseline: 1.7524x; 1.0480x over previous
#include <cuda_runtime.h>
#include <cuda_fp16.h>
#include <cstdint>

// Problem constants
#define GB 64
#define GN 196
#define GD 768
#define GH 12
#define GHD 64
#define GSIDE 14
#define GM (GB*GN)   // 12544

// Scratch (device globals: allocation-free rule)
__device__ __align__(16) __half g_q_h[GB*GH*GN*GHD];     // fp16 Q/8 head-major
__device__ __align__(16) __half g_k_h[GB*GH*GN*GHD];     // fp16 K head-major
__device__ __align__(16) __half g_vt_h[GB*GH*GHD*GN];    // fp16 V transposed [head][64][196]
__device__ __align__(16) __half g_hs_h[(size_t)GM*GD];   // fp16 hidden states
__device__ __align__(16) __half g_wt_h[4*GD*GD];         // fp16 transposed weights [N][K]
__device__ __align__(16) __half g_ctx_h[(size_t)GM*GD];  // fp16 ctx

// ============================ helpers =======================================
__device__ __forceinline__ uint32_t smem_u32(const void* p) {
    uint32_t a;
    asm("{ .reg .u64 t; cvta.to.shared.u64 t, %1; cvt.u32.u64 %0, t; }" : "=r"(a) : "l"(p));
    return a;
}
__device__ __forceinline__ void cp16(uint32_t s, const void* g) {
    asm volatile("cp.async.cg.shared.global [%0], [%1], 16;" :: "r"(s), "l"(g));
}
__device__ __forceinline__ void cp_commit() { asm volatile("cp.async.commit_group;" ::: "memory"); }
__device__ __forceinline__ void cp_wait1()  { asm volatile("cp.async.wait_group 1;"  ::: "memory"); }

__device__ __forceinline__ void mma_f16(float* c, const uint32_t* a, uint32_t b0, uint32_t b1) {
    asm volatile(
        "mma.sync.aligned.m16n8k16.row.col.f32.f16.f16.f32 "
        "{%0,%1,%2,%3}, {%4,%5,%6,%7}, {%8,%9}, {%0,%1,%2,%3};"
        : "+f"(c[0]), "+f"(c[1]), "+f"(c[2]), "+f"(c[3])
        : "r"(a[0]), "r"(a[1]), "r"(a[2]), "r"(a[3]), "r"(b0), "r"(b1));
}
__device__ __forceinline__ uint32_t h2_bits(float x, float y) {
    __half2 h = __floats2half2_rn(x, y);
    return *(uint32_t*)&h;
}

// ===================== conversion pre-passes ================================
__global__ void conv_f2h(const float* __restrict__ s, __half* __restrict__ d, int n4) {
    int i = blockIdx.x * blockDim.x + threadIdx.x;
    if (i < n4) {
        float4 v = ((const float4*)s)[i];
        __half2 lo = __floats2half2_rn(v.x, v.y);
        __half2 hi = __floats2half2_rn(v.z, v.w);
        uint2 o;
        o.x = *(uint32_t*)&lo;
        o.y = *(uint32_t*)&hi;
        ((uint2*)d)[i] = o;
    }
}

// 4 transposes in one launch: z selects the matrix
__global__ void transpose_f2h4(const float* __restrict__ W0, const float* __restrict__ W1,
                               const float* __restrict__ W2, const float* __restrict__ W3,
                               __half* __restrict__ T)
{
    __shared__ float tile[32][33];
    const float* S = (blockIdx.z == 0) ? W0 : (blockIdx.z == 1) ? W1 :
                     (blockIdx.z == 2) ? W2 : W3;
    __half* D = T + (size_t)blockIdx.z * GD * GD;
    int tx = threadIdx.x, ty = threadIdx.y;
    int x = blockIdx.x * 32 + tx;
    int y = blockIdx.y * 32 + ty;
    #pragma unroll
    for (int j = 0; j < 32; j += 8)
        tile[ty + j][tx] = S[(size_t)(y + j) * GD + x];
    __syncthreads();
    int x2 = blockIdx.y * 32 + tx;
    int y2 = blockIdx.x * 32 + ty;
    #pragma unroll
    for (int j = 0; j < 32; j += 8)
        D[(size_t)(y2 + j) * GD + x2] = __float2half(tile[tx][ty + j]);
}

// ===================== fp16 mma.sync GEMM core ==============================
#define BM 128
#define BN 128
#define HBK 64
#define HST 72
#define HASZ (BM*HST)
#define HBSZ (BN*HST)
#define GEMM_SMEM ((2*HASZ + 2*HBSZ)*2)   // 73728 B
#define NCH (GD/HBK)                      // 12

struct GemmAcc { float a[2][8][4]; };

__device__ __forceinline__ void gemm_mainloop(
    const __half* __restrict__ Ag, const __half* __restrict__ Bg,
    __half* As, __half* Bs, GemmAcc& G)
{
    const uint32_t abase = smem_u32(As);
    const uint32_t bbase = smem_u32(Bs);
    const int tid = threadIdx.x;

    auto loadA = [&](int c, int buf) {
        const __half* ag = Ag + c*HBK;
        const uint32_t dst = abase + buf*HASZ*2;
        #pragma unroll
        for (int it = 0; it < 4; it++) {
            int idx = tid + 256*it;
            int m = idx >> 3, k8 = idx & 7;
            cp16(dst + (m*HST + k8*8)*2, ag + (size_t)m*GD + k8*8);
        }
    };
    auto loadB = [&](int c, int buf) {
        const __half* bg = Bg + c*HBK;
        const uint32_t dst = bbase + buf*HBSZ*2;
        #pragma unroll
        for (int it = 0; it < 4; it++) {
            int idx = tid + 256*it;
            int n = idx >> 3, k8 = idx & 7;
            cp16(dst + (n*HST + k8*8)*2, bg + (size_t)n*GD + k8*8);
        }
    };

    loadA(0, 0); loadB(0, 0); cp_commit();
    loadA(1, 1); loadB(1, 1); cp_commit();

    const int wid = tid >> 5, lane = tid & 31;
    const int wm = wid & 3, wn = wid >> 2;
    const int lr = lane >> 2, lq = lane & 3;

    #pragma unroll
    for (int i = 0; i < 2; i++)
        #pragma unroll
        for (int j = 0; j < 8; j++)
            #pragma unroll
            for (int k = 0; k < 4; k++) G.a[i][j][k] = 0.f;

    for (int c = 0; c < NCH; c++) {
        cp_wait1();
        __syncthreads();
        const int buf = c & 1;
        const __half* as = As + buf*HASZ;
        const __half* bs = Bs + buf*HBSZ;

        #pragma unroll
        for (int s = 0; s < 4; s++) {
            const int k0 = s*16 + 2*lq;
            uint32_t a[2][4], b[8][2];
            #pragma unroll
            for (int mt = 0; mt < 2; mt++) {
                const int r = wm*32 + mt*16 + lr;
                a[mt][0] = *(const uint32_t*)&as[r*HST + k0];
                a[mt][1] = *(const uint32_t*)&as[(r+8)*HST + k0];
                a[mt][2] = *(const uint32_t*)&as[r*HST + k0 + 8];
                a[mt][3] = *(const uint32_t*)&as[(r+8)*HST + k0 + 8];
            }
            #pragma unroll
            for (int nt = 0; nt < 8; nt++) {
                const int n = wn*64 + nt*8 + lr;
                b[nt][0] = *(const uint32_t*)&bs[n*HST + k0];
                b[nt][1] = *(const uint32_t*)&bs[n*HST + k0 + 8];
            }
            #pragma unroll
            for (int mt = 0; mt < 2; mt++)
                #pragma unroll
                for (int nt = 0; nt < 8; nt++)
                    mma_f16(G.a[mt][nt], a[mt], b[nt][0], b[nt][1]);
        }
        __syncthreads();
        if (c + 2 < NCH) { loadA(c+2, buf); loadB(c+2, buf); }
        cp_commit();
    }
}

// Fused QKV GEMM. Q written PRE-SCALED by 1/8 (score scale folded in);
// K fp16 head-major; V fp16 TRANSPOSED.
__global__ void __launch_bounds__(256, 2)
mma_gemm_qkv(const __half* __restrict__ A, const __half* __restrict__ BT,
             const float* __restrict__ bq, const float* __restrict__ bk,
             const float* __restrict__ bv,
             __half* __restrict__ Cq, __half* __restrict__ Ck, __half* __restrict__ Cvt)
{
    extern __shared__ __half smh[];
    const int bx = blockIdx.x, by = blockIdx.y;
    const int mat = bx / 6;                  // 0=Q 1=K 2=V
    const float* bias = (mat == 0) ? bq : (mat == 1) ? bk : bv;
    const int bxm = bx - mat*6;
    const float oscale = (mat == 0) ? 0.125f : 1.f;

    GemmAcc G;
    gemm_mainloop(A + (size_t)(by*BM)*GD, BT + (size_t)(bx*BN)*GD,
                  smh, smh + 2*HASZ, G);

    const int tid = threadIdx.x, wid = tid >> 5, lane = tid & 31;
    const int wm = wid & 3, wn = wid >> 2;
    const int lr = lane >> 2, lq = lane & 3;

    #pragma unroll
    for (int mt = 0; mt < 2; mt++) {
        #pragma unroll
        for (int h8 = 0; h8 < 2; h8++) {
            const int row = by*BM + wm*32 + mt*16 + h8*8 + lr;
            const int bb = row / GN, nn = row % GN;
            #pragma unroll
            for (int nt = 0; nt < 8; nt++) {
                const int col = bxm*BN + wn*64 + nt*8 + 2*lq;
                float vx = (G.a[mt][nt][h8*2+0] + bias[col]) * oscale;
                float vy = (G.a[mt][nt][h8*2+1] + bias[col+1]) * oscale;
                const int h = col >> 6, hd = col & 63;
                if (mat == 2) {
                    __half* vt = Cvt + (((size_t)bb*GH + h)*GHD)*GN;
                    vt[(size_t)hd*GN + nn]     = __float2half(vx);
                    vt[(size_t)(hd+1)*GN + nn] = __float2half(vy);
                } else {
                    __half* C = (mat == 0) ? Cq : Ck;
                    uint32_t bits = h2_bits(vx, vy);
                    *(uint32_t*)(C + (((size_t)bb*GH + h)*GN + nn)*GHD + hd) = bits;
                }
            }
        }
    }
}

// Output GEMM: fp32 output + bias
__global__ void __launch_bounds__(256, 2)
mma_gemm_out(const __half* __restrict__ A, const __half* __restrict__ BT,
             const float* __restrict__ bias, float* __restrict__ C)
{
    extern __shared__ __half smh[];
    const int bx = blockIdx.x, by = blockIdx.y;

    GemmAcc G;
    gemm_mainloop(A + (size_t)(by*BM)*GD, BT + (size_t)(bx*BN)*GD,
                  smh, smh + 2*HASZ, G);

    const int tid = threadIdx.x, wid = tid >> 5, lane = tid & 31;
    const int wm = wid & 3, wn = wid >> 2;
    const int lr = lane >> 2, lq = lane & 3;

    #pragma unroll
    for (int mt = 0; mt < 2; mt++) {
        #pragma unroll
        for (int h8 = 0; h8 < 2; h8++) {
            const int row = by*BM + wm*32 + mt*16 + h8*8 + lr;
            #pragma unroll
            for (int nt = 0; nt < 8; nt++) {
                const int col = bx*BN + wn*64 + nt*8 + 2*lq;
                float2 v;
                v.x = G.a[mt][nt][h8*2+0] + bias[col];
                v.y = G.a[mt][nt][h8*2+1] + bias[col+1];
                *(float2*)(C + (size_t)row*GD + col) = v;
            }
        }
    }
}

// ============ Flash-mma attention, no-max softmax ===========================
// Logits v = mask*s are bounded (|v| ~< 6): softmax computed WITHOUT
// max-subtraction -> no running max, no ctx rescale, no serial chain.
// CTA = 128 thr / 4 warps, 64 query rows; grid = 768 heads x 4 chunks.
#define AKST 72
#define AVST 216
#define ATT_SMEM (200*AKST*2 + 64*AVST*2 + 64*4)   // 56960 B

__global__ void __launch_bounds__(128)
attn_flash(const __half* __restrict__ Qh, const __half* __restrict__ Kh,
           const __half* __restrict__ Vth, const float* __restrict__ Wsig,
           const float* __restrict__ bsigp, const float* __restrict__ tempp,
           __half* __restrict__ CTX)
{
    extern __shared__ __half smh[];
    __half* Ks = smh;                       // [200][72]
    __half* Vt = smh + 200*AKST;            // [64][216]
    float* invden = (float*)(smh + 200*AKST + 64*AVST);  // [64]

    const int bh = blockIdx.x >> 2, chunk = blockIdx.x & 3;
    const __half* Qg  = Qh  + (size_t)bh * GN * GHD;
    const __half* Kg  = Kh  + (size_t)bh * GN * GHD;
    const __half* Vtg = Vth + (size_t)bh * GHD * GN;

    const int tid = threadIdx.x;

    // ---- prologue loads ----
    for (int idx = tid; idx < GN*32; idx += 128) {
        int j = idx >> 5, dp = idx & 31;
        *(uint32_t*)&Ks[j*AKST + 2*dp] = *(const uint32_t*)&Kg[j*GHD + 2*dp];
    }
    for (int idx = tid; idx < GHD*98; idx += 128) {
        int d = idx / 98, jp = idx - d*98;
        *(uint32_t*)&Vt[d*AVST + 2*jp] = *(const uint32_t*)&Vtg[d*GN + 2*jp];
    }
    for (int idx = tid; idx < GHD*10; idx += 128) {
        int d = idx / 10, c = idx - d*10;
        *(uint32_t*)&Vt[d*AVST + GN + 2*c] = 0u;
    }
    // ---- sigma -> -1/denom (Q is pre-scaled by 1/8: compensate with *8) ----
    if (tid < 64) {
        int r = chunk*64 + tid;
        if (r > GN-1) r = GN-1;
        const __half* qr = Qg + r*GHD;
        float acc = 0.f;
        #pragma unroll 8
        for (int dp = 0; dp < 32; dp++) {
            float2 q = __half22float2(*(const __half2*)&qr[2*dp]);
            float2 w = *(const float2*)&Wsig[2*dp];
            acc += q.x*w.x + q.y*w.y;
        }
        float x = acc*8.f + bsigp[0];
        float sp = (x > 20.f) ? x : log1pf(expf(x));
        float sg = (sp + 1e-3f) * tempp[0];
        invden[tid] = -1.f / (2.f*sg*sg);
    }
    __syncthreads();

    const int w = tid >> 5, lane = tid & 31;
    const int m0 = chunk*64 + w*16;
    if (m0 >= GN) return;    // warp-uniform; no further CTA syncs

    const int lr = lane >> 2, lq = lane & 3;
    const int row_lo = m0 + lr, row_hi = row_lo + 8;
    const int rlo = (row_lo > GN-1) ? GN-1 : row_lo;
    const int rhi = (row_hi > GN-1) ? GN-1 : row_hi;
    const float ivd_lo = invden[w*16 + lr];
    const float ivd_hi = invden[w*16 + lr + 8];
    const int iy_lo = (rlo*2341) >> 15, ix_lo = rlo - GSIDE*iy_lo;
    const int iy_hi = (rhi*2341) >> 15, ix_hi = rhi - GSIDE*iy_hi;

    // ---- Q A-fragments ----
    uint32_t qa[4][4];
    {
        const __half* qlo = Qg + rlo*GHD + 2*lq;
        const __half* qhi = Qg + rhi*GHD + 2*lq;
        #pragma unroll
        for (int ks = 0; ks < 4; ks++) {
            qa[ks][0] = *(const uint32_t*)&qlo[16*ks];
            qa[ks][1] = *(const uint32_t*)&qhi[16*ks];
            qa[ks][2] = *(const uint32_t*)&qlo[16*ks + 8];
            qa[ks][3] = *(const uint32_t*)&qhi[16*ks + 8];
        }
    }

    float ctx[8][4];
    #pragma unroll
    for (int nt = 0; nt < 8; nt++)
        #pragma unroll
        for (int c = 0; c < 4; c++) ctx[nt][c] = 0.f;
    float l_lo = 0.f, l_hi = 0.f;

    #pragma unroll 1
    for (int pr = 0; pr < 13; pr++) {
        // ---- S for 16 cols [16pr, 16pr+16) ----
        float sa[4] = {0.f,0.f,0.f,0.f}, sb[4] = {0.f,0.f,0.f,0.f};
        const __half* ka = Ks + (pr*16 + lr)*AKST + 2*lq;
        #pragma unroll
        for (int ks = 0; ks < 4; ks++)
            mma_f16(sa, qa[ks], *(const uint32_t*)&ka[16*ks],
                                *(const uint32_t*)&ka[16*ks + 8]);
        if (pr < 12) {
            const __half* kb = ka + 8*AKST;
            #pragma unroll
            for (int ks = 0; ks < 4; ks++)
                mma_f16(sb, qa[ks], *(const uint32_t*)&kb[16*ks],
                                    *(const uint32_t*)&kb[16*ks + 8]);
        }

        // ---- gaussian mask + direct exp (no max subtraction) ----
        const int j0 = pr*16 + 2*lq;
        float p[8];   // [t*2 + (0=lo,1=hi)] for t over {j0, j0+1, j0+8, j0+9}
        #pragma unroll
        for (int t = 0; t < 4; t++) {
            const int j = j0 + (t & 1) + ((t & 2) << 2);   // j0,j0+1,j0+8,j0+9
            const float s = (t & 2) ? sb[t & 1 ? 1 : 0] : sa[t & 1];
            const float s_hi = (t & 2) ? sb[(t & 1) + 2] : sa[(t & 1) + 2];
            if (j < GN) {
                const int jy = (j*2341) >> 15, jx = j - GSIDE*jy;
                const int dyl = iy_lo - jy, dxl = ix_lo - jx;
                const int dyh = iy_hi - jy, dxh = ix_hi - jx;
                const float mlo = __expf((float)(dyl*dyl + dxl*dxl) * ivd_lo);
                const float mhi = __expf((float)(dyh*dyh + dxh*dxh) * ivd_hi);
                p[t*2]   = __expf(mlo * s);
                p[t*2+1] = __expf(mhi * s_hi);
            } else {
                p[t*2] = 0.f;
                p[t*2+1] = 0.f;
            }
        }
        l_lo += (p[0] + p[2]) + (p[4] + p[6]);
        l_hi += (p[1] + p[3]) + (p[5] + p[7]);

        uint32_t pa[4];
        pa[0] = h2_bits(p[0], p[2]);   // row_lo, cols j0,j0+1
        pa[1] = h2_bits(p[1], p[3]);   // row_hi, cols j0,j0+1
        pa[2] = h2_bits(p[4], p[6]);   // row_lo, cols j0+8,j0+9
        pa[3] = h2_bits(p[5], p[7]);   // row_hi, cols j0+8,j0+9

        // ---- P*V k-step (no rescale) ----
        const __half* vbase = Vt + pr*16 + 2*lq;
        #pragma unroll
        for (int nt = 0; nt < 8; nt++) {
            const __half* vp = vbase + (nt*8 + lr)*AVST;
            mma_f16(ctx[nt], pa, *(const uint32_t*)&vp[0],
                                 *(const uint32_t*)&vp[8]);
        }
    }

    // ---- finalize ----
    l_lo += __shfl_xor_sync(0xffffffffu, l_lo, 1);
    l_lo += __shfl_xor_sync(0xffffffffu, l_lo, 2);
    l_hi += __shfl_xor_sync(0xffffffffu, l_hi, 1);
    l_hi += __shfl_xor_sync(0xffffffffu, l_hi, 2);
    const float il_lo = 1.f / l_lo, il_hi = 1.f / l_hi;

    const int b = bh / GH, h = bh % GH;
    __half* out_lo = CTX + ((size_t)(b*GN + row_lo))*GD + h*GHD + 2*lq;
    __half* out_hi = CTX + ((size_t)(b*GN + row_hi))*GD + h*GHD + 2*lq;
    #pragma unroll
    for (int nt = 0; nt < 8; nt++) {
        if (row_lo < GN)
            *(uint32_t*)&out_lo[nt*8] = h2_bits(ctx[nt][0]*il_lo, ctx[nt][1]*il_lo);
        if (row_hi < GN)
            *(uint32_t*)&out_hi[nt*8] = h2_bits(ctx[nt][2]*il_hi, ctx[nt][3]*il_hi);
    }
}

// ---------------- launch ----------------------------------------------------
extern "C" void kernel_launch(void* const* d_in, const int* in_sizes, int n_in,
                              void* d_out, int out_size)
{
    const float* hs   = (const float*)d_in[0];
    const float* temp = (const float*)d_in[1];
    const float* Wq   = (const float*)d_in[2];
    const float* bq   = (const float*)d_in[3];
    const float* Wk   = (const float*)d_in[4];
    const float* bk   = (const float*)d_in[5];
    const float* Wv   = (const float*)d_in[6];
    const float* bv   = (const float*)d_in[7];
    const float* Wo   = (const float*)d_in[8];
    const float* bo   = (const float*)d_in[9];
    const float* Wsig = (const float*)d_in[10];
    const float* bsig = (const float*)d_in[11];
    float* out = (float*)d_out;

    __half *gq, *gk, *gvt, *ghs, *gwt, *gctx;
    cudaGetSymbolAddress((void**)&gq,   g_q_h);
    cudaGetSymbolAddress((void**)&gk,   g_k_h);
    cudaGetSymbolAddress((void**)&gvt,  g_vt_h);
    cudaGetSymbolAddress((void**)&ghs,  g_hs_h);
    cudaGetSymbolAddress((void**)&gwt,  g_wt_h);
    cudaGetSymbolAddress((void**)&gctx, g_ctx_h);

    cudaFuncSetAttribute(attn_flash,
                         cudaFuncAttributeMaxDynamicSharedMemorySize, ATT_SMEM);
    cudaFuncSetAttribute(mma_gemm_qkv,
                         cudaFuncAttributeMaxDynamicSharedMemorySize, GEMM_SMEM);
    cudaFuncSetAttribute(mma_gemm_out,
                         cudaFuncAttributeMaxDynamicSharedMemorySize, GEMM_SMEM);

    __half* wto = gwt + 3ull*GD*GD;

    const int nhs4 = GM*GD/4;
    conv_f2h<<<(nhs4 + 255)/256, 256>>>(hs, ghs, nhs4);
    dim3 tb(32, 8), tg(GD/32, GD/32, 4);
    transpose_f2h4<<<tg, tb>>>(Wq, Wk, Wv, Wo, gwt);

    dim3 gqkv(3*GD/BN, GM/BM);   // (18, 98)
    mma_gemm_qkv<<<gqkv, 256, GEMM_SMEM>>>(ghs, gwt, bq, bk, bv, gq, gk, gvt);
    attn_flash<<<GB*GH*4, 128, ATT_SMEM>>>(gq, gk, gvt, Wsig, bsig, temp, gctx);
    dim3 gout(GD/BN, GM/BM);     // (6, 98)
    mma_gemm_out<<<gout, 256, GEMM_SMEM>>>(gctx, wto, bo, out);
}

// round 10
// speedup vs baseline: 1.9450x; 1.1099x over previous
#include <cuda_runtime.h>
#include <cuda_fp16.h>
#include <cstdint>

// Problem constants
#define GB 64
#define GN 196
#define GD 768
#define GH 12
#define GHD 64
#define GSIDE 14
#define GM (GB*GN)   // 12544

// Scratch (device globals: allocation-free rule)
__device__ __align__(16) __half g_q_h[GB*GH*GN*GHD];     // fp16 Q/8 head-major
__device__ __align__(16) __half g_k_h[GB*GH*GN*GHD];     // fp16 K head-major
__device__ __align__(16) __half g_vt_h[GB*GH*GHD*GN];    // fp16 V transposed [head][64][196]
__device__ __align__(16) __half g_hs_h[(size_t)GM*GD];   // fp16 hidden states
__device__ __align__(16) __half g_wt_h[4*GD*GD];         // fp16 transposed weights [N][K]
__device__ __align__(16) __half g_ctx_h[(size_t)GM*GD];  // fp16 ctx

// ============================ helpers =======================================
__device__ __forceinline__ uint32_t smem_u32(const void* p) {
    uint32_t a;
    asm("{ .reg .u64 t; cvta.to.shared.u64 t, %1; cvt.u32.u64 %0, t; }" : "=r"(a) : "l"(p));
    return a;
}
__device__ __forceinline__ void cp16(uint32_t s, const void* g) {
    asm volatile("cp.async.cg.shared.global [%0], [%1], 16;" :: "r"(s), "l"(g));
}
__device__ __forceinline__ void cp_commit() { asm volatile("cp.async.commit_group;" ::: "memory"); }
__device__ __forceinline__ void cp_wait1()  { asm volatile("cp.async.wait_group 1;"  ::: "memory"); }

__device__ __forceinline__ void mma_f16(float* c, const uint32_t* a, uint32_t b0, uint32_t b1) {
    asm volatile(
        "mma.sync.aligned.m16n8k16.row.col.f32.f16.f16.f32 "
        "{%0,%1,%2,%3}, {%4,%5,%6,%7}, {%8,%9}, {%0,%1,%2,%3};"
        : "+f"(c[0]), "+f"(c[1]), "+f"(c[2]), "+f"(c[3])
        : "r"(a[0]), "r"(a[1]), "r"(a[2]), "r"(a[3]), "r"(b0), "r"(b1));
}
__device__ __forceinline__ uint32_t h2_bits(float x, float y) {
    __half2 h = __floats2half2_rn(x, y);
    return *(uint32_t*)&h;
}

// ===================== conversion pre-passes ================================
__global__ void conv_f2h(const float* __restrict__ s, __half* __restrict__ d, int n4) {
    int i = blockIdx.x * blockDim.x + threadIdx.x;
    if (i < n4) {
        float4 v = ((const float4*)s)[i];
        __half2 lo = __floats2half2_rn(v.x, v.y);
        __half2 hi = __floats2half2_rn(v.z, v.w);
        uint2 o;
        o.x = *(uint32_t*)&lo;
        o.y = *(uint32_t*)&hi;
        ((uint2*)d)[i] = o;
    }
}

// 4 transposes in one launch: z selects the matrix
__global__ void transpose_f2h4(const float* __restrict__ W0, const float* __restrict__ W1,
                               const float* __restrict__ W2, const float* __restrict__ W3,
                               __half* __restrict__ T)
{
    __shared__ float tile[32][33];
    const float* S = (blockIdx.z == 0) ? W0 : (blockIdx.z == 1) ? W1 :
                     (blockIdx.z == 2) ? W2 : W3;
    __half* D = T + (size_t)blockIdx.z * GD * GD;
    int tx = threadIdx.x, ty = threadIdx.y;
    int x = blockIdx.x * 32 + tx;
    int y = blockIdx.y * 32 + ty;
    #pragma unroll
    for (int j = 0; j < 32; j += 8)
        tile[ty + j][tx] = S[(size_t)(y + j) * GD + x];
    __syncthreads();
    int x2 = blockIdx.y * 32 + tx;
    int y2 = blockIdx.x * 32 + ty;
    #pragma unroll
    for (int j = 0; j < 32; j += 8)
        D[(size_t)(y2 + j) * GD + x2] = __float2half(tile[tx][ty + j]);
}

// ===================== fp16 mma.sync GEMM core ==============================
#define BM 128
#define BN 128
#define HBK 64
#define HST 72
#define HASZ (BM*HST)
#define HBSZ (BN*HST)
#define GEMM_SMEM ((2*HASZ + 2*HBSZ)*2)   // 73728 B
#define NCH (GD/HBK)                      // 12

struct GemmAcc { float a[2][8][4]; };

__device__ __forceinline__ void gemm_mainloop(
    const __half* __restrict__ Ag, const __half* __restrict__ Bg,
    __half* As, __half* Bs, GemmAcc& G)
{
    const uint32_t abase = smem_u32(As);
    const uint32_t bbase = smem_u32(Bs);
    const int tid = threadIdx.x;

    auto loadA = [&](int c, int buf) {
        const __half* ag = Ag + c*HBK;
        const uint32_t dst = abase + buf*HASZ*2;
        #pragma unroll
        for (int it = 0; it < 4; it++) {
            int idx = tid + 256*it;
            int m = idx >> 3, k8 = idx & 7;
            cp16(dst + (m*HST + k8*8)*2, ag + (size_t)m*GD + k8*8);
        }
    };
    auto loadB = [&](int c, int buf) {
        const __half* bg = Bg + c*HBK;
        const uint32_t dst = bbase + buf*HBSZ*2;
        #pragma unroll
        for (int it = 0; it < 4; it++) {
            int idx = tid + 256*it;
            int n = idx >> 3, k8 = idx & 7;
            cp16(dst + (n*HST + k8*8)*2, bg + (size_t)n*GD + k8*8);
        }
    };

    loadA(0, 0); loadB(0, 0); cp_commit();
    loadA(1, 1); loadB(1, 1); cp_commit();

    const int wid = tid >> 5, lane = tid & 31;
    const int wm = wid & 3, wn = wid >> 2;
    const int lr = lane >> 2, lq = lane & 3;

    #pragma unroll
    for (int i = 0; i < 2; i++)
        #pragma unroll
        for (int j = 0; j < 8; j++)
            #pragma unroll
            for (int k = 0; k < 4; k++) G.a[i][j][k] = 0.f;

    for (int c = 0; c < NCH; c++) {
        cp_wait1();
        __syncthreads();
        const int buf = c & 1;
        const __half* as = As + buf*HASZ;
        const __half* bs = Bs + buf*HBSZ;

        #pragma unroll
        for (int s = 0; s < 4; s++) {
            const int k0 = s*16 + 2*lq;
            uint32_t a[2][4], b[8][2];
            #pragma unroll
            for (int mt = 0; mt < 2; mt++) {
                const int r = wm*32 + mt*16 + lr;
                a[mt][0] = *(const uint32_t*)&as[r*HST + k0];
                a[mt][1] = *(const uint32_t*)&as[(r+8)*HST + k0];
                a[mt][2] = *(const uint32_t*)&as[r*HST + k0 + 8];
                a[mt][3] = *(const uint32_t*)&as[(r+8)*HST + k0 + 8];
            }
            #pragma unroll
            for (int nt = 0; nt < 8; nt++) {
                const int n = wn*64 + nt*8 + lr;
                b[nt][0] = *(const uint32_t*)&bs[n*HST + k0];
                b[nt][1] = *(const uint32_t*)&bs[n*HST + k0 + 8];
            }
            #pragma unroll
            for (int mt = 0; mt < 2; mt++)
                #pragma unroll
                for (int nt = 0; nt < 8; nt++)
                    mma_f16(G.a[mt][nt], a[mt], b[nt][0], b[nt][1]);
        }
        __syncthreads();
        if (c + 2 < NCH) { loadA(c+2, buf); loadB(c+2, buf); }
        cp_commit();
    }
}

// Fused QKV GEMM. Q written PRE-SCALED by 1/8; K head-major; V TRANSPOSED.
__global__ void __launch_bounds__(256, 2)
mma_gemm_qkv(const __half* __restrict__ A, const __half* __restrict__ BT,
             const float* __restrict__ bq, const float* __restrict__ bk,
             const float* __restrict__ bv,
             __half* __restrict__ Cq, __half* __restrict__ Ck, __half* __restrict__ Cvt)
{
    extern __shared__ __half smh[];
    const int bx = blockIdx.x, by = blockIdx.y;
    const int mat = bx / 6;                  // 0=Q 1=K 2=V
    const float* bias = (mat == 0) ? bq : (mat == 1) ? bk : bv;
    const int bxm = bx - mat*6;
    const float oscale = (mat == 0) ? 0.125f : 1.f;

    GemmAcc G;
    gemm_mainloop(A + (size_t)(by*BM)*GD, BT + (size_t)(bx*BN)*GD,
                  smh, smh + 2*HASZ, G);

    const int tid = threadIdx.x, wid = tid >> 5, lane = tid & 31;
    const int wm = wid & 3, wn = wid >> 2;
    const int lr = lane >> 2, lq = lane & 3;

    #pragma unroll
    for (int mt = 0; mt < 2; mt++) {
        #pragma unroll
        for (int h8 = 0; h8 < 2; h8++) {
            const int row = by*BM + wm*32 + mt*16 + h8*8 + lr;
            const int bb = row / GN, nn = row % GN;
            #pragma unroll
            for (int nt = 0; nt < 8; nt++) {
                const int col = bxm*BN + wn*64 + nt*8 + 2*lq;
                float vx = (G.a[mt][nt][h8*2+0] + bias[col]) * oscale;
                float vy = (G.a[mt][nt][h8*2+1] + bias[col+1]) * oscale;
                const int h = col >> 6, hd = col & 63;
                if (mat == 2) {
                    __half* vt = Cvt + (((size_t)bb*GH + h)*GHD)*GN;
                    vt[(size_t)hd*GN + nn]     = __float2half(vx);
                    vt[(size_t)(hd+1)*GN + nn] = __float2half(vy);
                } else {
                    __half* C = (mat == 0) ? Cq : Ck;
                    uint32_t bits = h2_bits(vx, vy);
                    *(uint32_t*)(C + (((size_t)bb*GH + h)*GN + nn)*GHD + hd) = bits;
                }
            }
        }
    }
}

// Output GEMM: fp32 output + bias
__global__ void __launch_bounds__(256, 2)
mma_gemm_out(const __half* __restrict__ A, const __half* __restrict__ BT,
             const float* __restrict__ bias, float* __restrict__ C)
{
    extern __shared__ __half smh[];
    const int bx = blockIdx.x, by = blockIdx.y;

    GemmAcc G;
    gemm_mainloop(A + (size_t)(by*BM)*GD, BT + (size_t)(bx*BN)*GD,
                  smh, smh + 2*HASZ, G);

    const int tid = threadIdx.x, wid = tid >> 5, lane = tid & 31;
    const int wm = wid & 3, wn = wid >> 2;
    const int lr = lane >> 2, lq = lane & 3;

    #pragma unroll
    for (int mt = 0; mt < 2; mt++) {
        #pragma unroll
        for (int h8 = 0; h8 < 2; h8++) {
            const int row = by*BM + wm*32 + mt*16 + h8*8 + lr;
            #pragma unroll
            for (int nt = 0; nt < 8; nt++) {
                const int col = bx*BN + wn*64 + nt*8 + 2*lq;
                float2 v;
                v.x = G.a[mt][nt][h8*2+0] + bias[col];
                v.y = G.a[mt][nt][h8*2+1] + bias[col+1];
                *(float2*)(C + (size_t)row*GD + col) = v;
            }
        }
    }
}

// ============ Flash-mma attention, no-max softmax, 8-warp CTA ===============
// CTA = 256 thr / 8 warps sharing one K/V tile; CTA covers 128 query rows.
// Grid = 768 heads x 2 chunks (rows 0-127 / 128-195). Warp stripe = 16 rows.
#define AKST 72
#define AVST 216
#define ATT_SMEM (200*AKST*2 + 64*AVST*2 + 128*4)   // 57216 B

__global__ void __launch_bounds__(256, 3)
attn_flash(const __half* __restrict__ Qh, const __half* __restrict__ Kh,
           const __half* __restrict__ Vth, const float* __restrict__ Wsig,
           const float* __restrict__ bsigp, const float* __restrict__ tempp,
           __half* __restrict__ CTX)
{
    extern __shared__ __half smh[];
    __half* Ks = smh;                       // [200][72]
    __half* Vt = smh + 200*AKST;            // [64][216]
    float* invden = (float*)(smh + 200*AKST + 64*AVST);  // [128]

    const int bh = blockIdx.x >> 1, chunk = blockIdx.x & 1;
    const __half* Qg  = Qh  + (size_t)bh * GN * GHD;
    const __half* Kg  = Kh  + (size_t)bh * GN * GHD;
    const __half* Vtg = Vth + (size_t)bh * GHD * GN;

    const int tid = threadIdx.x;

    // ---- prologue loads (256 threads) ----
    for (int idx = tid; idx < GN*32; idx += 256) {
        int j = idx >> 5, dp = idx & 31;
        *(uint32_t*)&Ks[j*AKST + 2*dp] = *(const uint32_t*)&Kg[j*GHD + 2*dp];
    }
    for (int idx = tid; idx < GHD*98; idx += 256) {
        int d = idx / 98, jp = idx - d*98;
        *(uint32_t*)&Vt[d*AVST + 2*jp] = *(const uint32_t*)&Vtg[d*GN + 2*jp];
    }
    for (int idx = tid; idx < GHD*10; idx += 256) {
        int d = idx / 10, c = idx - d*10;
        *(uint32_t*)&Vt[d*AVST + GN + 2*c] = 0u;
    }
    // ---- sigma -> -1/denom (Q pre-scaled by 1/8: compensate *8) ----
    if (tid < 128) {
        int r = chunk*128 + tid;
        if (r > GN-1) r = GN-1;
        const __half* qr = Qg + r*GHD;
        float acc = 0.f;
        #pragma unroll 8
        for (int dp = 0; dp < 32; dp++) {
            float2 q = __half22float2(*(const __half2*)&qr[2*dp]);
            float2 w = *(const float2*)&Wsig[2*dp];
            acc += q.x*w.x + q.y*w.y;
        }
        float x = acc*8.f + bsigp[0];
        float sp = (x > 20.f) ? x : log1pf(expf(x));
        float sg = (sp + 1e-3f) * tempp[0];
        invden[tid] = -1.f / (2.f*sg*sg);
    }
    __syncthreads();

    const int w = tid >> 5, lane = tid & 31;
    const int m0 = chunk*128 + w*16;
    if (m0 >= GN) return;    // warp-uniform; no further CTA syncs

    const int lr = lane >> 2, lq = lane & 3;
    const int row_lo = m0 + lr, row_hi = row_lo + 8;
    const int rlo = (row_lo > GN-1) ? GN-1 : row_lo;
    const int rhi = (row_hi > GN-1) ? GN-1 : row_hi;
    const float ivd_lo = invden[w*16 + lr];
    const float ivd_hi = invden[w*16 + lr + 8];
    const int iy_lo = (rlo*2341) >> 15, ix_lo = rlo - GSIDE*iy_lo;
    const int iy_hi = (rhi*2341) >> 15, ix_hi = rhi - GSIDE*iy_hi;

    // ---- Q A-fragments ----
    uint32_t qa[4][4];
    {
        const __half* qlo = Qg + rlo*GHD + 2*lq;
        const __half* qhi = Qg + rhi*GHD + 2*lq;
        #pragma unroll
        for (int ks = 0; ks < 4; ks++) {
            qa[ks][0] = *(const uint32_t*)&qlo[16*ks];
            qa[ks][1] = *(const uint32_t*)&qhi[16*ks];
            qa[ks][2] = *(const uint32_t*)&qlo[16*ks + 8];
            qa[ks][3] = *(const uint32_t*)&qhi[16*ks + 8];
        }
    }

    float ctx[8][4];
    #pragma unroll
    for (int nt = 0; nt < 8; nt++)
        #pragma unroll
        for (int c = 0; c < 4; c++) ctx[nt][c] = 0.f;
    float l_lo = 0.f, l_hi = 0.f;

    #pragma unroll 1
    for (int pr = 0; pr < 13; pr++) {
        // ---- S for 16 cols [16pr, 16pr+16) ----
        float sa[4] = {0.f,0.f,0.f,0.f}, sb[4] = {0.f,0.f,0.f,0.f};
        const __half* ka = Ks + (pr*16 + lr)*AKST + 2*lq;
        #pragma unroll
        for (int ks = 0; ks < 4; ks++)
            mma_f16(sa, qa[ks], *(const uint32_t*)&ka[16*ks],
                                *(const uint32_t*)&ka[16*ks + 8]);
        if (pr < 12) {
            const __half* kb = ka + 8*AKST;
            #pragma unroll
            for (int ks = 0; ks < 4; ks++)
                mma_f16(sb, qa[ks], *(const uint32_t*)&kb[16*ks],
                                    *(const uint32_t*)&kb[16*ks + 8]);
        }

        // ---- gaussian mask + direct exp (no max subtraction) ----
        const int j0 = pr*16 + 2*lq;
        float p[8];
        #pragma unroll
        for (int t = 0; t < 4; t++) {
            const int j = j0 + (t & 1) + ((t & 2) << 2);   // j0,j0+1,j0+8,j0+9
            const float s = (t & 2) ? sb[t & 1 ? 1 : 0] : sa[t & 1];
            const float s_hi = (t & 2) ? sb[(t & 1) + 2] : sa[(t & 1) + 2];
            if (j < GN) {
                const int jy = (j*2341) >> 15, jx = j - GSIDE*jy;
                const int dyl = iy_lo - jy, dxl = ix_lo - jx;
                const int dyh = iy_hi - jy, dxh = ix_hi - jx;
                const float mlo = __expf((float)(dyl*dyl + dxl*dxl) * ivd_lo);
                const float mhi = __expf((float)(dyh*dyh + dxh*dxh) * ivd_hi);
                p[t*2]   = __expf(mlo * s);
                p[t*2+1] = __expf(mhi * s_hi);
            } else {
                p[t*2] = 0.f;
                p[t*2+1] = 0.f;
            }
        }
        l_lo += (p[0] + p[2]) + (p[4] + p[6]);
        l_hi += (p[1] + p[3]) + (p[5] + p[7]);

        uint32_t pa[4];
        pa[0] = h2_bits(p[0], p[2]);
        pa[1] = h2_bits(p[1], p[3]);
        pa[2] = h2_bits(p[4], p[6]);
        pa[3] = h2_bits(p[5], p[7]);

        // ---- P*V k-step ----
        const __half* vbase = Vt + pr*16 + 2*lq;
        #pragma unroll
        for (int nt = 0; nt < 8; nt++) {
            const __half* vp = vbase + (nt*8 + lr)*AVST;
            mma_f16(ctx[nt], pa, *(const uint32_t*)&vp[0],
                                 *(const uint32_t*)&vp[8]);
        }
    }

    // ---- finalize ----
    l_lo += __shfl_xor_sync(0xffffffffu, l_lo, 1);
    l_lo += __shfl_xor_sync(0xffffffffu, l_lo, 2);
    l_hi += __shfl_xor_sync(0xffffffffu, l_hi, 1);
    l_hi += __shfl_xor_sync(0xffffffffu, l_hi, 2);
    const float il_lo = 1.f / l_lo, il_hi = 1.f / l_hi;

    const int b = bh / GH, h = bh % GH;
    __half* out_lo = CTX + ((size_t)(b*GN + row_lo))*GD + h*GHD + 2*lq;
    __half* out_hi = CTX + ((size_t)(b*GN + row_hi))*GD + h*GHD + 2*lq;
    #pragma unroll
    for (int nt = 0; nt < 8; nt++) {
        if (row_lo < GN)
            *(uint32_t*)&out_lo[nt*8] = h2_bits(ctx[nt][0]*il_lo, ctx[nt][1]*il_lo);
        if (row_hi < GN)
            *(uint32_t*)&out_hi[nt*8] = h2_bits(ctx[nt][2]*il_hi, ctx[nt][3]*il_hi);
    }
}

// ---------------- launch ----------------------------------------------------
extern "C" void kernel_launch(void* const* d_in, const int* in_sizes, int n_in,
                              void* d_out, int out_size)
{
    const float* hs   = (const float*)d_in[0];
    const float* temp = (const float*)d_in[1];
    const float* Wq   = (const float*)d_in[2];
    const float* bq   = (const float*)d_in[3];
    const float* Wk   = (const float*)d_in[4];
    const float* bk   = (const float*)d_in[5];
    const float* Wv   = (const float*)d_in[6];
    const float* bv   = (const float*)d_in[7];
    const float* Wo   = (const float*)d_in[8];
    const float* bo   = (const float*)d_in[9];
    const float* Wsig = (const float*)d_in[10];
    const float* bsig = (const float*)d_in[11];
    float* out = (float*)d_out;

    __half *gq, *gk, *gvt, *ghs, *gwt, *gctx;
    cudaGetSymbolAddress((void**)&gq,   g_q_h);
    cudaGetSymbolAddress((void**)&gk,   g_k_h);
    cudaGetSymbolAddress((void**)&gvt,  g_vt_h);
    cudaGetSymbolAddress((void**)&ghs,  g_hs_h);
    cudaGetSymbolAddress((void**)&gwt,  g_wt_h);
    cudaGetSymbolAddress((void**)&gctx, g_ctx_h);

    cudaFuncSetAttribute(attn_flash,
                         cudaFuncAttributeMaxDynamicSharedMemorySize, ATT_SMEM);
    cudaFuncSetAttribute(mma_gemm_qkv,
                         cudaFuncAttributeMaxDynamicSharedMemorySize, GEMM_SMEM);
    cudaFuncSetAttribute(mma_gemm_out,
                         cudaFuncAttributeMaxDynamicSharedMemorySize, GEMM_SMEM);

    __half* wto = gwt + 3ull*GD*GD;

    const int nhs4 = GM*GD/4;
    conv_f2h<<<(nhs4 + 255)/256, 256>>>(hs, ghs, nhs4);
    dim3 tb(32, 8), tg(GD/32, GD/32, 4);
    transpose_f2h4<<<tg, tb>>>(Wq, Wk, Wv, Wo, gwt);

    dim3 gqkv(3*GD/BN, GM/BM);   // (18, 98)
    mma_gemm_qkv<<<gqkv, 256, GEMM_SMEM>>>(ghs, gwt, bq, bk, bv, gq, gk, gvt);
    attn_flash<<<GB*GH*2, 256, ATT_SMEM>>>(gq, gk, gvt, Wsig, bsig, temp, gctx);
    dim3 gout(GD/BN, GM/BM);     // (6, 98)
    mma_gemm_out<<<gout, 256, GEMM_SMEM>>>(gctx, wto, bo, out);
}